// round 9
// baseline (speedup 1.0000x reference)
#include <cuda_runtime.h>
#include <math.h>

#define HH 128
#define SS 65
#define SP 68          // padded S stride (cols 65..67 zero where read)
#define VTS 132        // transposed-V stride
#define NT 1024

typedef unsigned long long u64;

__device__ __forceinline__ u64 pack2(float lo, float hi) {
    u64 r; asm("mov.b64 %0, {%1, %2};" : "=l"(r) : "f"(lo), "f"(hi)); return r;
}
__device__ __forceinline__ float2 unpack2(u64 p) {
    float2 v; asm("mov.b64 {%0, %1}, %2;" : "=f"(v.x), "=f"(v.y) : "l"(p)); return v;
}
__device__ __forceinline__ u64 fma2(u64 a, u64 b, u64 c) {
    u64 d; asm("fma.rn.f32x2 %0, %1, %2, %3;" : "=l"(d) : "l"(a), "l"(b), "l"(c)); return d;
}
__device__ __forceinline__ float dot4(const float4& a, const float4& b, float acc) {
    acc = fmaf(a.x, b.x, acc);
    acc = fmaf(a.y, b.y, acc);
    acc = fmaf(a.z, b.z, acc);
    acc = fmaf(a.w, b.w, acc);
    return acc;
}

#define PF_L1(p) asm volatile("prefetch.global.L1 [%0];" :: "l"(p))

#define ACC_MAT(AR, Bx, By, Bz, Bw, ACC)                                              \
    do {                                                                              \
        u64 p_;                                                                       \
        p_ = pack2(AR.x, AR.x); ACC[0] = fma2(p_, Bx.x, ACC[0]); ACC[1] = fma2(p_, Bx.y, ACC[1]); \
        p_ = pack2(AR.y, AR.y); ACC[0] = fma2(p_, By.x, ACC[0]); ACC[1] = fma2(p_, By.y, ACC[1]); \
        p_ = pack2(AR.z, AR.z); ACC[0] = fma2(p_, Bz.x, ACC[0]); ACC[1] = fma2(p_, Bz.y, ACC[1]); \
        p_ = pack2(AR.w, AR.w); ACC[0] = fma2(p_, Bw.x, ACC[0]); ACC[1] = fma2(p_, Bw.y, ACC[1]); \
    } while (0)

// Fused K/Q/V projection, one Y sweep. Tiles: 2j x 4t, 1024 tiles = 1024 threads.
// K,Q stored [j][t] stride SP; V stored TRANSPOSED [t][j] stride VTS.
// Per-output chain: k ascending (bit-identical across tile shapes).
__device__ __forceinline__ void gemm_KQV(
    const float* __restrict__ Wk, const float* __restrict__ Wq, const float* __restrict__ Wv,
    const float* __restrict__ sY,
    float* __restrict__ sK, float* __restrict__ sQ, float* __restrict__ sVt) {
    {
        int tid = threadIdx.x;
        int j0 = (tid >> 4) << 1;        // 0..126, step 2
        int t0 = (tid & 15) << 2;        // 0..60
        u64 aK[2][2], aQ[2][2], aV[2][2];
        #pragma unroll
        for (int r = 0; r < 2; r++) {
            aK[r][0] = aK[r][1] = 0ull;
            aQ[r][0] = aQ[r][1] = 0ull;
            aV[r][0] = aV[r][1] = 0ull;
        }
        #pragma unroll 1
        for (int k = 0; k < HH; k += 4) {
            ulonglong2 b0 = *(const ulonglong2*)(sY + (k + 0) * SP + t0);
            ulonglong2 b1 = *(const ulonglong2*)(sY + (k + 1) * SP + t0);
            ulonglong2 b2 = *(const ulonglong2*)(sY + (k + 2) * SP + t0);
            ulonglong2 b3 = *(const ulonglong2*)(sY + (k + 3) * SP + t0);
            #pragma unroll
            for (int r = 0; r < 2; r++) {
                float4 ak = *(const float4*)(Wk + (j0 + r) * HH + k);
                ACC_MAT(ak, b0, b1, b2, b3, aK[r]);
                float4 aq = *(const float4*)(Wq + (j0 + r) * HH + k);
                ACC_MAT(aq, b0, b1, b2, b3, aQ[r]);
                float4 av = *(const float4*)(Wv + (j0 + r) * HH + k);
                ACC_MAT(av, b0, b1, b2, b3, aV[r]);
            }
        }
        #pragma unroll
        for (int r = 0; r < 2; r++) {
            ulonglong2 o;
            o.x = aK[r][0]; o.y = aK[r][1]; *(ulonglong2*)(sK + (j0 + r) * SP + t0) = o;
            o.x = aQ[r][0]; o.y = aQ[r][1]; *(ulonglong2*)(sQ + (j0 + r) * SP + t0) = o;
        }
        // V transposed store (float2 columns)
        float av4[2][4];
        #pragma unroll
        for (int r = 0; r < 2; r++) {
            float2 lo = unpack2(aV[r][0]), hi = unpack2(aV[r][1]);
            av4[r][0] = lo.x; av4[r][1] = lo.y; av4[r][2] = hi.x; av4[r][3] = hi.y;
        }
        #pragma unroll
        for (int tt = 0; tt < 4; tt++) {
            float2 c; c.x = av4[0][tt]; c.y = av4[1][tt];
            *(float2*)(sVt + (t0 + tt) * VTS + j0) = c;
        }
    }
    // tail: t = 64; Vt pad rows zeroed
    if (threadIdx.x < HH) {
        int j = threadIdx.x;
        float cK = 0.f, cQ = 0.f, cV = 0.f;
        #pragma unroll 4
        for (int k = 0; k < HH; k += 4) {
            float y0 = sY[(k + 0) * SP + 64];
            float y1 = sY[(k + 1) * SP + 64];
            float y2 = sY[(k + 2) * SP + 64];
            float y3 = sY[(k + 3) * SP + 64];
            float4 wk4 = *(const float4*)(Wk + j * HH + k);
            cK = fmaf(wk4.x, y0, cK); cK = fmaf(wk4.y, y1, cK);
            cK = fmaf(wk4.z, y2, cK); cK = fmaf(wk4.w, y3, cK);
            float4 wq4 = *(const float4*)(Wq + j * HH + k);
            cQ = fmaf(wq4.x, y0, cQ); cQ = fmaf(wq4.y, y1, cQ);
            cQ = fmaf(wq4.z, y2, cQ); cQ = fmaf(wq4.w, y3, cQ);
            float4 wv4 = *(const float4*)(Wv + j * HH + k);
            cV = fmaf(wv4.x, y0, cV); cV = fmaf(wv4.y, y1, cV);
            cV = fmaf(wv4.z, y2, cV); cV = fmaf(wv4.w, y3, cV);
        }
        sK[j * SP + 64] = cK;
        sQ[j * SP + 64] = cQ;
        sVt[64 * VTS + j] = cV;
        sVt[65 * VTS + j] = 0.f;
        sVt[66 * VTS + j] = 0.f;
        sVt[67 * VTS + j] = 0.f;
    }
}

// Fused 2-matrix projection (layer-2 q2 both heads). Tiles 2j x 4t.
__device__ __forceinline__ void gemm_KQ2(
    const float* __restrict__ Wa, const float* __restrict__ Wb,
    const float* __restrict__ sY,
    float* __restrict__ sA, float* __restrict__ sB2) {
    {
        int tid = threadIdx.x;
        int j0 = (tid >> 4) << 1;
        int t0 = (tid & 15) << 2;
        u64 aA[2][2], aB[2][2];
        #pragma unroll
        for (int r = 0; r < 2; r++) {
            aA[r][0] = aA[r][1] = 0ull;
            aB[r][0] = aB[r][1] = 0ull;
        }
        #pragma unroll 1
        for (int k = 0; k < HH; k += 4) {
            ulonglong2 b0 = *(const ulonglong2*)(sY + (k + 0) * SP + t0);
            ulonglong2 b1 = *(const ulonglong2*)(sY + (k + 1) * SP + t0);
            ulonglong2 b2 = *(const ulonglong2*)(sY + (k + 2) * SP + t0);
            ulonglong2 b3 = *(const ulonglong2*)(sY + (k + 3) * SP + t0);
            #pragma unroll
            for (int r = 0; r < 2; r++) {
                float4 wa = *(const float4*)(Wa + (j0 + r) * HH + k);
                ACC_MAT(wa, b0, b1, b2, b3, aA[r]);
                float4 wb = *(const float4*)(Wb + (j0 + r) * HH + k);
                ACC_MAT(wb, b0, b1, b2, b3, aB[r]);
            }
        }
        #pragma unroll
        for (int r = 0; r < 2; r++) {
            ulonglong2 o;
            o.x = aA[r][0]; o.y = aA[r][1]; *(ulonglong2*)(sA  + (j0 + r) * SP + t0) = o;
            o.x = aB[r][0]; o.y = aB[r][1]; *(ulonglong2*)(sB2 + (j0 + r) * SP + t0) = o;
        }
    }
    if (threadIdx.x < HH) {
        int j = threadIdx.x;
        float cA = 0.f, cB = 0.f;
        #pragma unroll 4
        for (int k = 0; k < HH; k += 4) {
            float y0 = sY[(k + 0) * SP + 64];
            float y1 = sY[(k + 1) * SP + 64];
            float y2 = sY[(k + 2) * SP + 64];
            float y3 = sY[(k + 3) * SP + 64];
            float4 wa4 = *(const float4*)(Wa + j * HH + k);
            cA = fmaf(wa4.x, y0, cA); cA = fmaf(wa4.y, y1, cA);
            cA = fmaf(wa4.z, y2, cA); cA = fmaf(wa4.w, y3, cA);
            float4 wb4 = *(const float4*)(Wb + j * HH + k);
            cB = fmaf(wb4.x, y0, cB); cB = fmaf(wb4.y, y1, cB);
            cB = fmaf(wb4.z, y2, cB); cB = fmaf(wb4.w, y3, cB);
        }
        sA[j * SP + 64]  = cA;
        sB2[j * SP + 64] = cB;
    }
}

// Row-wise softmax on one row (65 real cols), warp-collective. Zeroes pads.
__device__ __forceinline__ void softmax_row(float* __restrict__ row, int lane) {
    float v0 = row[lane], v1 = row[lane + 32], v2 = row[64];
    float m = fmaxf(fmaxf(v0, v1), v2);
    #pragma unroll
    for (int o = 16; o; o >>= 1) m = fmaxf(m, __shfl_xor_sync(0xffffffffu, m, o));
    float e0 = expf(v0 - m), e1 = expf(v1 - m), e2 = expf(v2 - m);
    float sum = e0 + e1;
    #pragma unroll
    for (int o = 16; o; o >>= 1) sum += __shfl_xor_sync(0xffffffffu, sum, o);
    float denom = sum + e2;
    row[lane] = e0 / denom;
    row[lane + 32] = e1 / denom;
    if (lane == 0) { row[64] = e2 / denom; row[65] = 0.f; row[66] = 0.f; row[67] = 0.f; }
}

// Fused kq -> softmax -> O, barrier-free (warp row-ownership; 32 warps).
// warp w owns rows 2w, 2w+1; warp 0 additionally owns row 64 end-to-end.
__device__ __forceinline__ void attn_fused(const float* __restrict__ sK,
                                           const float* __restrict__ sQ,
                                           const float* __restrict__ sVt,
                                           float* __restrict__ sKQ,
                                           float* __restrict__ sO) {
    int tid = threadIdx.x, w = tid >> 5, lane = tid & 31;
    int s0 = w << 1, t2 = lane << 1;

    // ---- kq main: rows s0, s0+1, cols t2, t2+1 (chain i ascending)
    {
        u64 a0 = 0ull, a1 = 0ull;
        #pragma unroll 4
        for (int i = 0; i < HH; i++) {
            float2 kv = *(const float2*)(sK + i * SP + s0);
            u64 q = *(const u64*)(sQ + i * SP + t2);
            a0 = fma2(pack2(kv.x, kv.x), q, a0);
            a1 = fma2(pack2(kv.y, kv.y), q, a1);
        }
        *(u64*)(sKQ + (s0 + 0) * SP + t2) = a0;
        *(u64*)(sKQ + (s0 + 1) * SP + t2) = a1;
    }
    // col 64 for own rows (lanes 0..1, scalar in-order)
    if (lane < 2) {
        int s = s0 + lane;
        float acc = 0.f;
        #pragma unroll 8
        for (int i = 0; i < HH; i++)
            acc = fmaf(sK[i * SP + s], sQ[i * SP + 64], acc);
        sKQ[s * SP + 64] = acc;
    }
    // row 64 (warp 0): packed pairs per lane + corner by lane 0
    if (w == 0) {
        u64 acc = 0ull;
        #pragma unroll 8
        for (int i = 0; i < HH; i++) {
            float kk = sK[i * SP + 64];
            acc = fma2(pack2(kk, kk), *(const u64*)(sQ + i * SP + t2), acc);
        }
        *(u64*)(sKQ + 64 * SP + t2) = acc;
        if (lane == 0) {
            float a = 0.f;
            #pragma unroll 8
            for (int i = 0; i < HH; i++)
                a = fmaf(sK[i * SP + 64], sQ[i * SP + 64], a);
            sKQ[64 * SP + 64] = a;
        }
    }
    __syncwarp();

    // ---- softmax on own rows
    softmax_row(sKQ + (s0 + 0) * SP, lane);
    softmax_row(sKQ + (s0 + 1) * SP, lane);
    if (w == 0) softmax_row(sKQ + 64 * SP, lane);
    __syncwarp();

    // ---- O: rows s0, s0+1, i0 = lane*4, packed over i-pairs, chain t ascending
    {
        int i0 = lane << 2;
        u64 o[2][2];
        o[0][0] = o[0][1] = o[1][0] = o[1][1] = 0ull;
        #pragma unroll 1
        for (int tb = 0; tb < SP; tb += 4) {
            float4 q0 = *(const float4*)(sKQ + (s0 + 0) * SP + tb);
            float4 q1 = *(const float4*)(sKQ + (s0 + 1) * SP + tb);
            float p0[4] = {q0.x, q0.y, q0.z, q0.w};
            float p1[4] = {q1.x, q1.y, q1.z, q1.w};
            #pragma unroll
            for (int tt = 0; tt < 4; tt++) {
                ulonglong2 vv = *(const ulonglong2*)(sVt + (tb + tt) * VTS + i0);
                u64 pp;
                pp = pack2(p0[tt], p0[tt]); o[0][0] = fma2(pp, vv.x, o[0][0]); o[0][1] = fma2(pp, vv.y, o[0][1]);
                pp = pack2(p1[tt], p1[tt]); o[1][0] = fma2(pp, vv.x, o[1][0]); o[1][1] = fma2(pp, vv.y, o[1][1]);
            }
        }
        ulonglong2 ov;
        ov.x = o[0][0]; ov.y = o[0][1]; *(ulonglong2*)(sO + (s0 + 0) * HH + i0) = ov;
        ov.x = o[1][0]; ov.y = o[1][1]; *(ulonglong2*)(sO + (s0 + 1) * HH + i0) = ov;
        // row 64 (warp 0)
        if (w == 0) {
            u64 oa = 0ull, ob = 0ull;
            #pragma unroll 1
            for (int tb = 0; tb < SP; tb += 4) {
                float4 q = *(const float4*)(sKQ + 64 * SP + tb);
                float pr[4] = {q.x, q.y, q.z, q.w};
                #pragma unroll
                for (int tt = 0; tt < 4; tt++) {
                    ulonglong2 vv = *(const ulonglong2*)(sVt + (tb + tt) * VTS + i0);
                    u64 pp = pack2(pr[tt], pr[tt]);
                    oa = fma2(pp, vv.x, oa);
                    ob = fma2(pp, vv.y, ob);
                }
            }
            ulonglong2 o64; o64.x = oa; o64.y = ob;
            *(ulonglong2*)(sO + 64 * HH + i0) = o64;
        }
    }
}

// sZ[s*HH + j] (FIRST: =, else continue chain) sum_i sO[s*HH+i] * L[i*HH+j]
// 32 warps x 2 rows; j0 = lane*4. Tail: row 64 on threads < 128.
template <int FIRST>
__device__ __forceinline__ void gemm_Z(const float* __restrict__ sO,
                                       const float* __restrict__ L,
                                       float* __restrict__ sZ) {
    {
        int tid = threadIdx.x;
        int s0 = (tid >> 5) << 1;        // 0..62
        int j0 = (tid & 31) << 2;        // 0..124
        u64 acc[2][2];
        #pragma unroll
        for (int r = 0; r < 2; r++) {
            if (FIRST) { acc[r][0] = 0ull; acc[r][1] = 0ull; }
            else {
                ulonglong2 z = *(const ulonglong2*)(sZ + (s0 + r) * HH + j0);
                acc[r][0] = z.x; acc[r][1] = z.y;
            }
        }
        #pragma unroll 1
        for (int i = 0; i < HH; i += 4) {
            if (i + 16 < HH) {
                PF_L1(L + (i + 16) * HH + j0);
                PF_L1(L + (i + 17) * HH + j0);
                PF_L1(L + (i + 18) * HH + j0);
                PF_L1(L + (i + 19) * HH + j0);
            }
            ulonglong2 l0 = *(const ulonglong2*)(L + (i + 0) * HH + j0);
            ulonglong2 l1 = *(const ulonglong2*)(L + (i + 1) * HH + j0);
            ulonglong2 l2 = *(const ulonglong2*)(L + (i + 2) * HH + j0);
            ulonglong2 l3 = *(const ulonglong2*)(L + (i + 3) * HH + j0);
            #pragma unroll
            for (int r = 0; r < 2; r++) {
                float4 o = *(const float4*)(sO + (s0 + r) * HH + i);
                ACC_MAT(o, l0, l1, l2, l3, acc[r]);
            }
        }
        #pragma unroll
        for (int r = 0; r < 2; r++) {
            ulonglong2 o; o.x = acc[r][0]; o.y = acc[r][1];
            *(ulonglong2*)(sZ + (s0 + r) * HH + j0) = o;
        }
    }
    // tail: s = 64 (same tid -> same element across FIRST/continue, no sync needed)
    if (threadIdx.x < HH) {
        int j = threadIdx.x;
        float acc = FIRST ? 0.f : sZ[64 * HH + j];
        #pragma unroll 8
        for (int i = 0; i < HH; i++)
            acc = fmaf(sO[64 * HH + i], L[i * HH + j], acc);
        sZ[64 * HH + j] = acc;
    }
}

// smem layout (floats):
//  P0 @     0 : 8704  Y -> O1 (stride 128)
//  P1 @  8704 : 8704  K0 -> K1 -> Z (stride 128)
//  P2 @ 17408 : 8704  Q0 -> Q1 -> Y2
//  P3 @ 26112 : 8976  V0t -> V1t -> q2a
//  P4 @ 35088 : 8704  O0 -> q2b
//  KQ @ 43792 : 4624
//  EX @ 48416 : 1120
#define SMEM_FLOATS 49536

__global__ void __launch_bounds__(NT, 1) board_kernel(
    const float* __restrict__ inp, const float* __restrict__ emb,
    const float* __restrict__ wk11, const float* __restrict__ wq11, const float* __restrict__ wv11,
    const float* __restrict__ wk12, const float* __restrict__ wq12, const float* __restrict__ wv12,
    const float* __restrict__ L1,
    const float* __restrict__ wk21, const float* __restrict__ wq21, const float* __restrict__ wv21,
    const float* __restrict__ wk22, const float* __restrict__ wq22, const float* __restrict__ wv22,
    const float* __restrict__ L2, const float* __restrict__ L3, const float* __restrict__ L4,
    float* __restrict__ out) {
    extern __shared__ float sm[];
    float* P0  = sm;
    float* P1  = sm + 8704;
    float* P2  = sm + 17408;
    float* P3  = sm + 26112;
    float* P4  = sm + 35088;
    float* sKQ = sm + 43792;
    float* sEX = sm + 48416;

    float* sc   = sEX;          // 2 x 128
    float* sw   = sEX + 256;    // 2 x 72 (stride 72)
    float* syw  = sEX + 416;    // 2 x 128
    float* satt = sEX + 672;    // 256
    float* sh2  = sEX + 928;    // 128
    float* sh3  = sEX + 1056;   // 64

    const int b = blockIdx.x;
    const int tid = threadIdx.x;
    const float* x = inp + (size_t)b * 64;

    // Y[j][s] = emb[j][s] * x[s], x[64]=1; padding cols zero.
    for (int idx = tid; idx < HH * SP; idx += NT) {
        int j = idx / SP, s = idx - j * SP;
        float v = 0.f;
        if (s < 64)       v = emb[j * 65 + s] * x[s];
        else if (s == 64) v = emb[j * 65 + 64];
        P0[idx] = v;
    }
    __syncthreads();

    // ---- layer 1, head 0 ----
    gemm_KQV(wk11, wq11, wv11, P0, P1, P2, P3);   // K0, Q0, V0t
    __syncthreads();
    attn_fused(P1, P2, P3, sKQ, P4);              // O0 -> P4
    __syncthreads();

    // ---- layer 1, head 1 ----
    gemm_KQV(wk12, wq12, wv12, P0, P1, P2, P3);   // K1, Q1, V1t
    __syncthreads();
    attn_fused(P1, P2, P3, sKQ, P0);              // O1 -> P0 (Y dead)
    __syncthreads();

    // Z = O0 @ L1[:128] then += O1 @ L1[128:] (single 256-deep in-order chain)
    gemm_Z<1>(P4, L1,           P1);
    gemm_Z<0>(P0, L1 + HH * HH, P1);              // row-ownership identical: no sync
    __syncthreads();

    // tanh + transpose: Y2[j][s] = tanh(Z[s][j]) -> P2
    for (int idx = tid; idx < HH * SP; idx += NT) {
        int j = idx / SP, s = idx - j * SP;
        P2[idx] = (s < SS) ? tanhf(P1[s * HH + j]) : 0.f;
    }
    __syncthreads();

    // ---- layer 2: both heads merged ----
    if (tid < 2 * HH) {                           // c[h][i] = Wk2h[i,:] . y64 (in-order)
        int h = tid >> 7, i = tid & 127;
        const float* Wk = h ? wk22 : wk21;
        float acc = 0.f;
        #pragma unroll 8
        for (int j = 0; j < HH; j++)
            acc = fmaf(Wk[i * HH + j], P2[j * SP + 64], acc);
        sc[(h << 7) + i] = acc;
    }
    gemm_KQ2(wq21, wq22, P2, P3, P4);             // q2a -> P3, q2b -> P4
    __syncthreads();

    if (tid < 2 * SS) {                           // logits[h][t] = c[h] . q2h[:,t]
        int h = tid >= SS, t = tid - (h ? SS : 0);
        const float* q2 = h ? P4 : P3;
        const float* ch = sc + (h << 7);
        float acc = 0.f;
        #pragma unroll 8
        for (int i = 0; i < HH; i++)
            acc = fmaf(ch[i], q2[i * SP + t], acc);
        sw[h * 72 + t] = acc;
    }
    __syncthreads();
    if (tid < 64) {                               // softmax rows (warps 0,1)
        int h = tid >> 5, lane = tid & 31;
        softmax_row(sw + h * 72, lane);
    }
    __syncthreads();
    if (tid < 2 * HH) {                           // yw[h][j] = sum_t w[h][t] * Y2[j][t]
        int h = tid >> 7, j = tid & 127;
        const float* wrow = sw + h * 72;
        float acc = 0.f;
        #pragma unroll
        for (int t = 0; t < SP; t += 4) {
            float4 y4 = *(const float4*)(P2 + j * SP + t);
            float4 w4 = *(const float4*)(wrow + t);
            acc = dot4(y4, w4, acc);
        }
        syw[(h << 7) + j] = acc;
    }
    __syncthreads();
    if (tid < 2 * HH) {                           // att[h][i] = Wv2h[i,:] . yw[h]
        int h = tid >> 7, i = tid & 127;
        const float* Wv = h ? wv22 : wv21;
        const float* yh = syw + (h << 7);
        float acc = 0.f;
        #pragma unroll 8
        for (int j = 0; j < HH; j += 4) {
            float4 w4 = *(const float4*)(Wv + i * HH + j);
            float4 y4 = *(const float4*)(yh + j);
            acc = dot4(w4, y4, acc);
        }
        satt[(h << 7) + i] = acc;
    }
    __syncthreads();

    // head: h2 = tanh(cat(att) @ L2), h3 = tanh(h2 @ L3), score = h3 @ L4
    if (tid < HH) {
        float acc = 0.f;
        #pragma unroll 8
        for (int i = 0; i < 2 * HH; i++)
            acc = fmaf(satt[i], L2[i * HH + tid], acc);
        sh2[tid] = tanhf(acc);
    }
    __syncthreads();
    if (tid < 64) {
        float acc = 0.f;
        #pragma unroll 8
        for (int j = 0; j < HH; j++)
            acc = fmaf(sh2[j], L3[j * 64 + tid], acc);
        sh3[tid] = tanhf(acc);
    }
    __syncthreads();
    if (tid == 0) {
        float acc = 0.f;
        #pragma unroll
        for (int m = 0; m < 64; m++) acc = fmaf(sh3[m], L4[m], acc);
        out[b] = acc;
    }
}

extern "C" void kernel_launch(void* const* d_in, const int* in_sizes, int n_in,
                              void* d_out, int out_size) {
    const float* inputs = (const float*)d_in[0];
    const float* emb    = (const float*)d_in[1];
    const float* wk11   = (const float*)d_in[2];
    const float* wq11   = (const float*)d_in[3];
    const float* wv11   = (const float*)d_in[4];
    const float* wk12   = (const float*)d_in[5];
    const float* wq12   = (const float*)d_in[6];
    const float* wv12   = (const float*)d_in[7];
    const float* L1     = (const float*)d_in[8];
    const float* wk21   = (const float*)d_in[9];
    const float* wq21   = (const float*)d_in[10];
    const float* wv21   = (const float*)d_in[11];
    const float* wk22   = (const float*)d_in[12];
    const float* wq22   = (const float*)d_in[13];
    const float* wv22   = (const float*)d_in[14];
    const float* L2     = (const float*)d_in[15];
    const float* L3     = (const float*)d_in[16];
    const float* L4     = (const float*)d_in[17];
    (void)n_in; (void)in_sizes;

    int B = out_size;  // one score per board (8192)

    size_t smem = SMEM_FLOATS * sizeof(float);
    cudaFuncSetAttribute(board_kernel, cudaFuncAttributeMaxDynamicSharedMemorySize, (int)smem);

    board_kernel<<<B, NT, smem>>>(inputs, emb,
                                  wk11, wq11, wv11, wk12, wq12, wv12, L1,
                                  wk21, wq21, wv21, wk22, wq22, wv22, L2, L3, L4,
                                  (float*)d_out);
}

// round 10
// speedup vs baseline: 1.0100x; 1.0100x over previous
#include <cuda_runtime.h>
#include <math.h>

#define HH 128
#define SS 65
#define SP 68          // padded S stride (cols 65..67 zero where read)
#define VTS 132        // transposed-V stride
#define NT 512

typedef unsigned long long u64;

__device__ __forceinline__ u64 pack2(float lo, float hi) {
    u64 r; asm("mov.b64 %0, {%1, %2};" : "=l"(r) : "f"(lo), "f"(hi)); return r;
}
__device__ __forceinline__ float2 unpack2(u64 p) {
    float2 v; asm("mov.b64 {%0, %1}, %2;" : "=f"(v.x), "=f"(v.y) : "l"(p)); return v;
}
__device__ __forceinline__ u64 fma2(u64 a, u64 b, u64 c) {
    u64 d; asm("fma.rn.f32x2 %0, %1, %2, %3;" : "=l"(d) : "l"(a), "l"(b), "l"(c)); return d;
}
__device__ __forceinline__ float dot4(const float4& a, const float4& b, float acc) {
    acc = fmaf(a.x, b.x, acc);
    acc = fmaf(a.y, b.y, acc);
    acc = fmaf(a.z, b.z, acc);
    acc = fmaf(a.w, b.w, acc);
    return acc;
}

#define PF_L1(p) asm volatile("prefetch.global.L1 [%0];" :: "l"(p))

// acc[0..3] (8 packed outputs) += broadcast(a) * B[0..3]; pack once, use 4x.
__device__ __forceinline__ void acc8(float a, const u64* __restrict__ B, u64* __restrict__ acc) {
    u64 p = pack2(a, a);
    acc[0] = fma2(p, B[0], acc[0]);
    acc[1] = fma2(p, B[1], acc[1]);
    acc[2] = fma2(p, B[2], acc[2]);
    acc[3] = fma2(p, B[3], acc[3]);
}
__device__ __forceinline__ void ld_row8(const float* __restrict__ p, u64* __restrict__ y) {
    ulonglong2 a = *(const ulonglong2*)(p);
    ulonglong2 b = *(const ulonglong2*)(p + 4);
    y[0] = a.x; y[1] = a.y; y[2] = b.x; y[3] = b.y;
}

// Fused K/Q/V projection, one Y sweep. Tiles: 2j x 8t, 512 tiles = 512 threads.
// K,Q stored [j][t] stride SP; V stored TRANSPOSED [t][j] stride VTS.
// Per-output chain: k ascending (bit-identical across tile shapes).
__device__ __forceinline__ void gemm_KQV(
    const float* __restrict__ Wk, const float* __restrict__ Wq, const float* __restrict__ Wv,
    const float* __restrict__ sY,
    float* __restrict__ sK, float* __restrict__ sQ, float* __restrict__ sVt) {
    {
        int tid = threadIdx.x;
        int j0 = (tid >> 3) << 1;        // 0..126, step 2
        int t0 = (tid & 7) << 3;         // 0..56
        u64 aK[2][4], aQ[2][4], aV[2][4];
        #pragma unroll
        for (int r = 0; r < 2; r++)
            #pragma unroll
            for (int c = 0; c < 4; c++) { aK[r][c] = 0ull; aQ[r][c] = 0ull; aV[r][c] = 0ull; }
        #pragma unroll 1
        for (int k = 0; k < HH; k += 4) {
            u64 y0[4], y1[4], y2[4], y3[4];
            ld_row8(sY + (k + 0) * SP + t0, y0);
            ld_row8(sY + (k + 1) * SP + t0, y1);
            ld_row8(sY + (k + 2) * SP + t0, y2);
            ld_row8(sY + (k + 3) * SP + t0, y3);
            #pragma unroll
            for (int r = 0; r < 2; r++) {
                float4 ak = *(const float4*)(Wk + (j0 + r) * HH + k);
                acc8(ak.x, y0, aK[r]); acc8(ak.y, y1, aK[r]);
                acc8(ak.z, y2, aK[r]); acc8(ak.w, y3, aK[r]);
                float4 aq = *(const float4*)(Wq + (j0 + r) * HH + k);
                acc8(aq.x, y0, aQ[r]); acc8(aq.y, y1, aQ[r]);
                acc8(aq.z, y2, aQ[r]); acc8(aq.w, y3, aQ[r]);
                float4 av = *(const float4*)(Wv + (j0 + r) * HH + k);
                acc8(av.x, y0, aV[r]); acc8(av.y, y1, aV[r]);
                acc8(av.z, y2, aV[r]); acc8(av.w, y3, aV[r]);
            }
        }
        #pragma unroll
        for (int r = 0; r < 2; r++) {
            ulonglong2 o;
            o.x = aK[r][0]; o.y = aK[r][1]; *(ulonglong2*)(sK + (j0 + r) * SP + t0)     = o;
            o.x = aK[r][2]; o.y = aK[r][3]; *(ulonglong2*)(sK + (j0 + r) * SP + t0 + 4) = o;
            o.x = aQ[r][0]; o.y = aQ[r][1]; *(ulonglong2*)(sQ + (j0 + r) * SP + t0)     = o;
            o.x = aQ[r][2]; o.y = aQ[r][3]; *(ulonglong2*)(sQ + (j0 + r) * SP + t0 + 4) = o;
        }
        // V transposed store: 8 rows of float2 (j0, j0+1)
        float v0[8], v1[8];
        #pragma unroll
        for (int c = 0; c < 4; c++) {
            float2 a = unpack2(aV[0][c]); v0[c * 2] = a.x; v0[c * 2 + 1] = a.y;
            float2 b = unpack2(aV[1][c]); v1[c * 2] = b.x; v1[c * 2 + 1] = b.y;
        }
        #pragma unroll
        for (int tt = 0; tt < 8; tt++) {
            float2 c; c.x = v0[tt]; c.y = v1[tt];
            *(float2*)(sVt + (t0 + tt) * VTS + j0) = c;
        }
    }
    // tail: t = 64; Vt pad rows zeroed
    if (threadIdx.x < HH) {
        int j = threadIdx.x;
        float cK = 0.f, cQ = 0.f, cV = 0.f;
        #pragma unroll 4
        for (int k = 0; k < HH; k += 4) {
            float y0 = sY[(k + 0) * SP + 64];
            float y1 = sY[(k + 1) * SP + 64];
            float y2 = sY[(k + 2) * SP + 64];
            float y3 = sY[(k + 3) * SP + 64];
            float4 wk4 = *(const float4*)(Wk + j * HH + k);
            cK = fmaf(wk4.x, y0, cK); cK = fmaf(wk4.y, y1, cK);
            cK = fmaf(wk4.z, y2, cK); cK = fmaf(wk4.w, y3, cK);
            float4 wq4 = *(const float4*)(Wq + j * HH + k);
            cQ = fmaf(wq4.x, y0, cQ); cQ = fmaf(wq4.y, y1, cQ);
            cQ = fmaf(wq4.z, y2, cQ); cQ = fmaf(wq4.w, y3, cQ);
            float4 wv4 = *(const float4*)(Wv + j * HH + k);
            cV = fmaf(wv4.x, y0, cV); cV = fmaf(wv4.y, y1, cV);
            cV = fmaf(wv4.z, y2, cV); cV = fmaf(wv4.w, y3, cV);
        }
        sK[j * SP + 64] = cK;
        sQ[j * SP + 64] = cQ;
        sVt[64 * VTS + j] = cV;
        sVt[65 * VTS + j] = 0.f;
        sVt[66 * VTS + j] = 0.f;
        sVt[67 * VTS + j] = 0.f;
    }
}

// Fused 2-matrix projection (layer-2 q2 both heads). Tiles 2j x 8t.
__device__ __forceinline__ void gemm_KQ2(
    const float* __restrict__ Wa, const float* __restrict__ Wb,
    const float* __restrict__ sY,
    float* __restrict__ sA, float* __restrict__ sB2) {
    {
        int tid = threadIdx.x;
        int j0 = (tid >> 3) << 1;
        int t0 = (tid & 7) << 3;
        u64 aA[2][4], aB[2][4];
        #pragma unroll
        for (int r = 0; r < 2; r++)
            #pragma unroll
            for (int c = 0; c < 4; c++) { aA[r][c] = 0ull; aB[r][c] = 0ull; }
        #pragma unroll 1
        for (int k = 0; k < HH; k += 4) {
            u64 y0[4], y1[4], y2[4], y3[4];
            ld_row8(sY + (k + 0) * SP + t0, y0);
            ld_row8(sY + (k + 1) * SP + t0, y1);
            ld_row8(sY + (k + 2) * SP + t0, y2);
            ld_row8(sY + (k + 3) * SP + t0, y3);
            #pragma unroll
            for (int r = 0; r < 2; r++) {
                float4 wa = *(const float4*)(Wa + (j0 + r) * HH + k);
                acc8(wa.x, y0, aA[r]); acc8(wa.y, y1, aA[r]);
                acc8(wa.z, y2, aA[r]); acc8(wa.w, y3, aA[r]);
                float4 wb = *(const float4*)(Wb + (j0 + r) * HH + k);
                acc8(wb.x, y0, aB[r]); acc8(wb.y, y1, aB[r]);
                acc8(wb.z, y2, aB[r]); acc8(wb.w, y3, aB[r]);
            }
        }
        #pragma unroll
        for (int r = 0; r < 2; r++) {
            ulonglong2 o;
            o.x = aA[r][0]; o.y = aA[r][1]; *(ulonglong2*)(sA  + (j0 + r) * SP + t0)     = o;
            o.x = aA[r][2]; o.y = aA[r][3]; *(ulonglong2*)(sA  + (j0 + r) * SP + t0 + 4) = o;
            o.x = aB[r][0]; o.y = aB[r][1]; *(ulonglong2*)(sB2 + (j0 + r) * SP + t0)     = o;
            o.x = aB[r][2]; o.y = aB[r][3]; *(ulonglong2*)(sB2 + (j0 + r) * SP + t0 + 4) = o;
        }
    }
    if (threadIdx.x < HH) {
        int j = threadIdx.x;
        float cA = 0.f, cB = 0.f;
        #pragma unroll 4
        for (int k = 0; k < HH; k += 4) {
            float y0 = sY[(k + 0) * SP + 64];
            float y1 = sY[(k + 1) * SP + 64];
            float y2 = sY[(k + 2) * SP + 64];
            float y3 = sY[(k + 3) * SP + 64];
            float4 wa4 = *(const float4*)(Wa + j * HH + k);
            cA = fmaf(wa4.x, y0, cA); cA = fmaf(wa4.y, y1, cA);
            cA = fmaf(wa4.z, y2, cA); cA = fmaf(wa4.w, y3, cA);
            float4 wb4 = *(const float4*)(Wb + j * HH + k);
            cB = fmaf(wb4.x, y0, cB); cB = fmaf(wb4.y, y1, cB);
            cB = fmaf(wb4.z, y2, cB); cB = fmaf(wb4.w, y3, cB);
        }
        sA[j * SP + 64]  = cA;
        sB2[j * SP + 64] = cB;
    }
}

// Row-wise softmax on one row (65 real cols), warp-collective. Zeroes pads.
__device__ __forceinline__ void softmax_row(float* __restrict__ row, int lane) {
    float v0 = row[lane], v1 = row[lane + 32], v2 = row[64];
    float m = fmaxf(fmaxf(v0, v1), v2);
    #pragma unroll
    for (int o = 16; o; o >>= 1) m = fmaxf(m, __shfl_xor_sync(0xffffffffu, m, o));
    float e0 = expf(v0 - m), e1 = expf(v1 - m), e2 = expf(v2 - m);
    float sum = e0 + e1;
    #pragma unroll
    for (int o = 16; o; o >>= 1) sum += __shfl_xor_sync(0xffffffffu, sum, o);
    float denom = sum + e2;
    row[lane] = e0 / denom;
    row[lane + 32] = e1 / denom;
    if (lane == 0) { row[64] = e2 / denom; row[65] = 0.f; row[66] = 0.f; row[67] = 0.f; }
}

// Fused kq -> softmax -> O, barrier-free (warp row-ownership; 16 warps).
// warp w owns rows 4w..4w+3; warp 0 additionally owns row 64 end-to-end.
__device__ __forceinline__ void attn_fused(const float* __restrict__ sK,
                                           const float* __restrict__ sQ,
                                           const float* __restrict__ sVt,
                                           float* __restrict__ sKQ,
                                           float* __restrict__ sO) {
    int tid = threadIdx.x, w = tid >> 5, lane = tid & 31;
    int s0 = w << 2, t2 = lane << 1;

    // ---- kq main: rows s0..s0+3, cols t2, t2+1 (chain i ascending)
    {
        u64 a0 = 0ull, a1 = 0ull, a2 = 0ull, a3 = 0ull;
        #pragma unroll 4
        for (int i = 0; i < HH; i++) {
            float4 kv = *(const float4*)(sK + i * SP + s0);
            u64 q = *(const u64*)(sQ + i * SP + t2);
            a0 = fma2(pack2(kv.x, kv.x), q, a0);
            a1 = fma2(pack2(kv.y, kv.y), q, a1);
            a2 = fma2(pack2(kv.z, kv.z), q, a2);
            a3 = fma2(pack2(kv.w, kv.w), q, a3);
        }
        *(u64*)(sKQ + (s0 + 0) * SP + t2) = a0;
        *(u64*)(sKQ + (s0 + 1) * SP + t2) = a1;
        *(u64*)(sKQ + (s0 + 2) * SP + t2) = a2;
        *(u64*)(sKQ + (s0 + 3) * SP + t2) = a3;
    }
    // col 64 for own rows (lanes 0..3, scalar in-order)
    if (lane < 4) {
        int s = s0 + lane;
        float acc = 0.f;
        #pragma unroll 8
        for (int i = 0; i < HH; i++)
            acc = fmaf(sK[i * SP + s], sQ[i * SP + 64], acc);
        sKQ[s * SP + 64] = acc;
    }
    // row 64 (warp 0): packed pairs per lane + corner by lane 0
    if (w == 0) {
        u64 acc = 0ull;
        #pragma unroll 8
        for (int i = 0; i < HH; i++) {
            float kk = sK[i * SP + 64];
            acc = fma2(pack2(kk, kk), *(const u64*)(sQ + i * SP + t2), acc);
        }
        *(u64*)(sKQ + 64 * SP + t2) = acc;
        if (lane == 0) {
            float a = 0.f;
            #pragma unroll 8
            for (int i = 0; i < HH; i++)
                a = fmaf(sK[i * SP + 64], sQ[i * SP + 64], a);
            sKQ[64 * SP + 64] = a;
        }
    }
    __syncwarp();

    // ---- softmax on own rows
    #pragma unroll
    for (int r = 0; r < 4; r++) softmax_row(sKQ + (s0 + r) * SP, lane);
    if (w == 0) softmax_row(sKQ + 64 * SP, lane);
    __syncwarp();

    // ---- O: rows s0..s0+3, i0 = lane*4, packed over i-pairs, chain t ascending
    {
        int i0 = lane << 2;
        u64 o[4][2];
        #pragma unroll
        for (int r = 0; r < 4; r++) { o[r][0] = 0ull; o[r][1] = 0ull; }
        #pragma unroll 1
        for (int tb = 0; tb < SP; tb += 4) {
            float4 q0 = *(const float4*)(sKQ + (s0 + 0) * SP + tb);
            float4 q1 = *(const float4*)(sKQ + (s0 + 1) * SP + tb);
            float4 q2v = *(const float4*)(sKQ + (s0 + 2) * SP + tb);
            float4 q3 = *(const float4*)(sKQ + (s0 + 3) * SP + tb);
            float p0[4] = {q0.x, q0.y, q0.z, q0.w};
            float p1[4] = {q1.x, q1.y, q1.z, q1.w};
            float p2[4] = {q2v.x, q2v.y, q2v.z, q2v.w};
            float p3[4] = {q3.x, q3.y, q3.z, q3.w};
            #pragma unroll
            for (int tt = 0; tt < 4; tt++) {
                ulonglong2 vv = *(const ulonglong2*)(sVt + (tb + tt) * VTS + i0);
                u64 pp;
                pp = pack2(p0[tt], p0[tt]); o[0][0] = fma2(pp, vv.x, o[0][0]); o[0][1] = fma2(pp, vv.y, o[0][1]);
                pp = pack2(p1[tt], p1[tt]); o[1][0] = fma2(pp, vv.x, o[1][0]); o[1][1] = fma2(pp, vv.y, o[1][1]);
                pp = pack2(p2[tt], p2[tt]); o[2][0] = fma2(pp, vv.x, o[2][0]); o[2][1] = fma2(pp, vv.y, o[2][1]);
                pp = pack2(p3[tt], p3[tt]); o[3][0] = fma2(pp, vv.x, o[3][0]); o[3][1] = fma2(pp, vv.y, o[3][1]);
            }
        }
        #pragma unroll
        for (int r = 0; r < 4; r++) {
            ulonglong2 ov; ov.x = o[r][0]; ov.y = o[r][1];
            *(ulonglong2*)(sO + (s0 + r) * HH + i0) = ov;
        }
        // row 64 (warp 0)
        if (w == 0) {
            u64 oa = 0ull, ob = 0ull;
            #pragma unroll 1
            for (int tb = 0; tb < SP; tb += 4) {
                float4 q = *(const float4*)(sKQ + 64 * SP + tb);
                float pr[4] = {q.x, q.y, q.z, q.w};
                #pragma unroll
                for (int tt = 0; tt < 4; tt++) {
                    ulonglong2 vv = *(const ulonglong2*)(sVt + (tb + tt) * VTS + i0);
                    u64 pp = pack2(pr[tt], pr[tt]);
                    oa = fma2(pp, vv.x, oa);
                    ob = fma2(pp, vv.y, ob);
                }
            }
            ulonglong2 o64; o64.x = oa; o64.y = ob;
            *(ulonglong2*)(sO + 64 * HH + i0) = o64;
        }
    }
}

// sZ[s*HH + j] (FIRST: =, else continue chain) sum_i sO[s*HH+i] * L[i*HH+j]
// Tiles 2s x 8j: 32 s-strips x 16 j-tiles = 512. Tail: row 64 on threads < 128.
template <int FIRST>
__device__ __forceinline__ void gemm_Z(const float* __restrict__ sO,
                                       const float* __restrict__ L,
                                       float* __restrict__ sZ) {
    {
        int tid = threadIdx.x;
        int s0 = (tid >> 4) << 1;        // 0..62
        int j0 = (tid & 15) << 3;        // 0..120
        u64 acc[2][4];
        #pragma unroll
        for (int r = 0; r < 2; r++) {
            if (FIRST) { acc[r][0] = acc[r][1] = acc[r][2] = acc[r][3] = 0ull; }
            else {
                ulonglong2 za = *(const ulonglong2*)(sZ + (s0 + r) * HH + j0);
                ulonglong2 zb = *(const ulonglong2*)(sZ + (s0 + r) * HH + j0 + 4);
                acc[r][0] = za.x; acc[r][1] = za.y; acc[r][2] = zb.x; acc[r][3] = zb.y;
            }
        }
        #pragma unroll 1
        for (int i = 0; i < HH; i += 4) {
            if (i + 16 < HH) {
                PF_L1(L + (i + 16) * HH + j0);
                PF_L1(L + (i + 17) * HH + j0);
                PF_L1(L + (i + 18) * HH + j0);
                PF_L1(L + (i + 19) * HH + j0);
            }
            u64 l0[4], l1[4], l2[4], l3[4];
            ld_row8(L + (i + 0) * HH + j0, l0);
            ld_row8(L + (i + 1) * HH + j0, l1);
            ld_row8(L + (i + 2) * HH + j0, l2);
            ld_row8(L + (i + 3) * HH + j0, l3);
            #pragma unroll
            for (int r = 0; r < 2; r++) {
                float4 o = *(const float4*)(sO + (s0 + r) * HH + i);
                acc8(o.x, l0, acc[r]); acc8(o.y, l1, acc[r]);
                acc8(o.z, l2, acc[r]); acc8(o.w, l3, acc[r]);
            }
        }
        #pragma unroll
        for (int r = 0; r < 2; r++) {
            ulonglong2 o;
            o.x = acc[r][0]; o.y = acc[r][1]; *(ulonglong2*)(sZ + (s0 + r) * HH + j0)     = o;
            o.x = acc[r][2]; o.y = acc[r][3]; *(ulonglong2*)(sZ + (s0 + r) * HH + j0 + 4) = o;
        }
    }
    // tail: s = 64 (same tid -> same element across FIRST/continue, no sync needed)
    if (threadIdx.x < HH) {
        int j = threadIdx.x;
        float acc = FIRST ? 0.f : sZ[64 * HH + j];
        #pragma unroll 8
        for (int i = 0; i < HH; i++)
            acc = fmaf(sO[64 * HH + i], L[i * HH + j], acc);
        sZ[64 * HH + j] = acc;
    }
}

// smem layout (floats):
//  P0 @     0 : 8704  Y -> O1 (stride 128)
//  P1 @  8704 : 8704  K0 -> K1 -> Z (stride 128)
//  P2 @ 17408 : 8704  Q0 -> Q1 -> Y2
//  P3 @ 26112 : 8976  V0t -> V1t -> q2a
//  P4 @ 35088 : 8704  O0 -> q2b
//  KQ @ 43792 : 4624
//  EX @ 48416 : 1120
#define SMEM_FLOATS 49536

__global__ void __launch_bounds__(NT, 1) board_kernel(
    const float* __restrict__ inp, const float* __restrict__ emb,
    const float* __restrict__ wk11, const float* __restrict__ wq11, const float* __restrict__ wv11,
    const float* __restrict__ wk12, const float* __restrict__ wq12, const float* __restrict__ wv12,
    const float* __restrict__ L1,
    const float* __restrict__ wk21, const float* __restrict__ wq21, const float* __restrict__ wv21,
    const float* __restrict__ wk22, const float* __restrict__ wq22, const float* __restrict__ wv22,
    const float* __restrict__ L2, const float* __restrict__ L3, const float* __restrict__ L4,
    float* __restrict__ out) {
    extern __shared__ float sm[];
    float* P0  = sm;
    float* P1  = sm + 8704;
    float* P2  = sm + 17408;
    float* P3  = sm + 26112;
    float* P4  = sm + 35088;
    float* sKQ = sm + 43792;
    float* sEX = sm + 48416;

    float* sc   = sEX;          // 2 x 128
    float* sw   = sEX + 256;    // 2 x 72 (stride 72)
    float* syw  = sEX + 416;    // 2 x 128
    float* satt = sEX + 672;    // 256
    float* sh2  = sEX + 928;    // 128
    float* sh3  = sEX + 1056;   // 64

    const int b = blockIdx.x;
    const int tid = threadIdx.x;
    const float* x = inp + (size_t)b * 64;

    // Y[j][s] = emb[j][s] * x[s], x[64]=1; padding cols zero.
    for (int idx = tid; idx < HH * SP; idx += NT) {
        int j = idx / SP, s = idx - j * SP;
        float v = 0.f;
        if (s < 64)       v = emb[j * 65 + s] * x[s];
        else if (s == 64) v = emb[j * 65 + 64];
        P0[idx] = v;
    }
    __syncthreads();

    // ---- layer 1, head 0 ----
    gemm_KQV(wk11, wq11, wv11, P0, P1, P2, P3);   // K0, Q0, V0t
    __syncthreads();
    attn_fused(P1, P2, P3, sKQ, P4);              // O0 -> P4
    __syncthreads();

    // ---- layer 1, head 1 ----
    gemm_KQV(wk12, wq12, wv12, P0, P1, P2, P3);   // K1, Q1, V1t
    __syncthreads();
    attn_fused(P1, P2, P3, sKQ, P0);              // O1 -> P0 (Y dead)
    __syncthreads();

    // Z = O0 @ L1[:128] then += O1 @ L1[128:] (single 256-deep in-order chain)
    gemm_Z<1>(P4, L1,           P1);
    gemm_Z<0>(P0, L1 + HH * HH, P1);              // row-ownership identical: no sync
    __syncthreads();

    // tanh + transpose: Y2[j][s] = tanh(Z[s][j]) -> P2
    for (int idx = tid; idx < HH * SP; idx += NT) {
        int j = idx / SP, s = idx - j * SP;
        P2[idx] = (s < SS) ? tanhf(P1[s * HH + j]) : 0.f;
    }
    __syncthreads();

    // ---- layer 2: both heads merged ----
    if (tid < 2 * HH) {                           // c[h][i] = Wk2h[i,:] . y64 (in-order)
        int h = tid >> 7, i = tid & 127;
        const float* Wk = h ? wk22 : wk21;
        float acc = 0.f;
        #pragma unroll 8
        for (int j = 0; j < HH; j++)
            acc = fmaf(Wk[i * HH + j], P2[j * SP + 64], acc);
        sc[(h << 7) + i] = acc;
    }
    gemm_KQ2(wq21, wq22, P2, P3, P4);             // q2a -> P3, q2b -> P4
    __syncthreads();

    if (tid < 2 * SS) {                           // logits[h][t] = c[h] . q2h[:,t]
        int h = tid >= SS, t = tid - (h ? SS : 0);
        const float* q2 = h ? P4 : P3;
        const float* ch = sc + (h << 7);
        float acc = 0.f;
        #pragma unroll 8
        for (int i = 0; i < HH; i++)
            acc = fmaf(ch[i], q2[i * SP + t], acc);
        sw[h * 72 + t] = acc;
    }
    __syncthreads();
    if (tid < 64) {                               // softmax rows (warps 0,1)
        int h = tid >> 5, lane = tid & 31;
        softmax_row(sw + h * 72, lane);
    }
    __syncthreads();
    if (tid < 2 * HH) {                           // yw[h][j] = sum_t w[h][t] * Y2[j][t]
        int h = tid >> 7, j = tid & 127;
        const float* wrow = sw + h * 72;
        float acc = 0.f;
        #pragma unroll
        for (int t = 0; t < SP; t += 4) {
            float4 y4 = *(const float4*)(P2 + j * SP + t);
            float4 w4 = *(const float4*)(wrow + t);
            acc = dot4(y4, w4, acc);
        }
        syw[(h << 7) + j] = acc;
    }
    __syncthreads();
    if (tid < 2 * HH) {                           // att[h][i] = Wv2h[i,:] . yw[h]
        int h = tid >> 7, i = tid & 127;
        const float* Wv = h ? wv22 : wv21;
        const float* yh = syw + (h << 7);
        float acc = 0.f;
        #pragma unroll 8
        for (int j = 0; j < HH; j += 4) {
            float4 w4 = *(const float4*)(Wv + i * HH + j);
            float4 y4 = *(const float4*)(yh + j);
            acc = dot4(w4, y4, acc);
        }
        satt[(h << 7) + i] = acc;
    }
    __syncthreads();

    // head: h2 = tanh(cat(att) @ L2), h3 = tanh(h2 @ L3), score = h3 @ L4
    if (tid < HH) {
        float acc = 0.f;
        #pragma unroll 8
        for (int i = 0; i < 2 * HH; i++)
            acc = fmaf(satt[i], L2[i * HH + tid], acc);
        sh2[tid] = tanhf(acc);
    }
    __syncthreads();
    if (tid < 64) {
        float acc = 0.f;
        #pragma unroll 8
        for (int j = 0; j < HH; j++)
            acc = fmaf(sh2[j], L3[j * 64 + tid], acc);
        sh3[tid] = tanhf(acc);
    }
    __syncthreads();
    if (tid == 0) {
        float acc = 0.f;
        #pragma unroll
        for (int m = 0; m < 64; m++) acc = fmaf(sh3[m], L4[m], acc);
        out[b] = acc;
    }
}

extern "C" void kernel_launch(void* const* d_in, const int* in_sizes, int n_in,
                              void* d_out, int out_size) {
    const float* inputs = (const float*)d_in[0];
    const float* emb    = (const float*)d_in[1];
    const float* wk11   = (const float*)d_in[2];
    const float* wq11   = (const float*)d_in[3];
    const float* wv11   = (const float*)d_in[4];
    const float* wk12   = (const float*)d_in[5];
    const float* wq12   = (const float*)d_in[6];
    const float* wv12   = (const float*)d_in[7];
    const float* L1     = (const float*)d_in[8];
    const float* wk21   = (const float*)d_in[9];
    const float* wq21   = (const float*)d_in[10];
    const float* wv21   = (const float*)d_in[11];
    const float* wk22   = (const float*)d_in[12];
    const float* wq22   = (const float*)d_in[13];
    const float* wv22   = (const float*)d_in[14];
    const float* L2     = (const float*)d_in[15];
    const float* L3     = (const float*)d_in[16];
    const float* L4     = (const float*)d_in[17];
    (void)n_in; (void)in_sizes;

    int B = out_size;  // one score per board (8192)

    size_t smem = SMEM_FLOATS * sizeof(float);
    cudaFuncSetAttribute(board_kernel, cudaFuncAttributeMaxDynamicSharedMemorySize, (int)smem);

    board_kernel<<<B, NT, smem>>>(inputs, emb,
                                  wk11, wq11, wv11, wk12, wq12, wv12, L1,
                                  wk21, wq21, wv21, wk22, wq22, wv22, L2, L3, L4,
                                  (float*)d_out);
}

// round 12
// speedup vs baseline: 1.2193x; 1.2072x over previous
#include <cuda_runtime.h>
#include <math.h>

#define HH 128
#define SS 65
#define SP 68          // padded S stride (cols 65..67 zero where read)
#define VTS 132        // transposed-V stride
#define NT 512

typedef unsigned long long u64;
typedef unsigned int u32;

__device__ __forceinline__ u64 pack2(float lo, float hi) {
    u64 r; asm("mov.b64 %0, {%1, %2};" : "=l"(r) : "f"(lo), "f"(hi)); return r;
}
__device__ __forceinline__ float2 unpack2(u64 p) {
    float2 v; asm("mov.b64 {%0, %1}, %2;" : "=f"(v.x), "=f"(v.y) : "l"(p)); return v;
}
__device__ __forceinline__ u64 fma2(u64 a, u64 b, u64 c) {
    u64 d; asm("fma.rn.f32x2 %0, %1, %2, %3;" : "=l"(d) : "l"(a), "l"(b), "l"(c)); return d;
}
__device__ __forceinline__ float dot4(const float4& a, const float4& b, float acc) {
    acc = fmaf(a.x, b.x, acc);
    acc = fmaf(a.y, b.y, acc);
    acc = fmaf(a.z, b.z, acc);
    acc = fmaf(a.w, b.w, acc);
    return acc;
}

#define PF_L1(p) asm volatile("prefetch.global.L1 [%0];" :: "l"(p))

__device__ __forceinline__ void cp16(u32 saddr, const float* g) {
    asm volatile("cp.async.cg.shared.global [%0], [%1], 16;" :: "r"(saddr), "l"(g));
}
#define CP_COMMIT() asm volatile("cp.async.commit_group;" ::: "memory")
#define CP_WAIT1()  asm volatile("cp.async.wait_group 1;" ::: "memory")
#define CP_WAIT0()  asm volatile("cp.async.wait_group 0;" ::: "memory")

#define ACC_MAT(AR, Bx, By, Bz, Bw, ACC)                                              \
    do {                                                                              \
        u64 p_;                                                                       \
        p_ = pack2(AR.x, AR.x); ACC[0] = fma2(p_, Bx.x, ACC[0]); ACC[1] = fma2(p_, Bx.y, ACC[1]); \
        p_ = pack2(AR.y, AR.y); ACC[0] = fma2(p_, By.x, ACC[0]); ACC[1] = fma2(p_, By.y, ACC[1]); \
        p_ = pack2(AR.z, AR.z); ACC[0] = fma2(p_, Bz.x, ACC[0]); ACC[1] = fma2(p_, Bz.y, ACC[1]); \
        p_ = pack2(AR.w, AR.w); ACC[0] = fma2(p_, Bw.x, ACC[0]); ACC[1] = fma2(p_, Bw.y, ACC[1]); \
    } while (0)

// ---- per-warp cp.async staging loaders (no barriers: each warp reads only its slice) ----
// KQV chunk: [3 mats][8 rows][8 k] floats = 192 floats = 48 float4 per stage.
__device__ __forceinline__ void kqv_issue(const float* __restrict__ Wk,
                                          const float* __restrict__ Wq,
                                          const float* __restrict__ Wv,
                                          int jbase, int k0, u32 dstB, int lane) {
    {
        int m = lane >> 4, sub = lane & 15, row = sub >> 1, half = sub & 1;
        const float* W = (m == 0) ? Wk : Wq;
        cp16(dstB + ((m * 64 + row * 8 + half * 4) << 2),
             W + (jbase + row) * HH + k0 + half * 4);
    }
    if (lane < 16) {
        int sub = lane;
        int row = sub >> 1, half = sub & 1;
        cp16(dstB + ((2 * 64 + row * 8 + half * 4) << 2),
             Wv + (jbase + row) * HH + k0 + half * 4);
    }
}
// KQ2 chunk: [2 mats][8 rows][8 k] = 128 floats = 32 float4 per stage.
__device__ __forceinline__ void kq2_issue(const float* __restrict__ Wa,
                                          const float* __restrict__ Wb,
                                          int jbase, int k0, u32 dstB, int lane) {
    int m = lane >> 4, sub = lane & 15, row = sub >> 1, half = sub & 1;
    const float* W = (m == 0) ? Wa : Wb;
    cp16(dstB + ((m * 64 + row * 8 + half * 4) << 2),
         W + (jbase + row) * HH + k0 + half * 4);
}

// Fused K/Q/V projection, one Y sweep, weights staged smem<-L2 via per-warp cp.async.
// Tiles (round-8 mapping): j0=(tid>>4)<<2, t0=(tid&15)<<2. Chains: k ascending (bit-identical).
__device__ __forceinline__ void gemm_KQV(
    const float* __restrict__ Wk, const float* __restrict__ Wq, const float* __restrict__ Wv,
    const float* __restrict__ sY,
    float* __restrict__ sK, float* __restrict__ sQ, float* __restrict__ sVt,
    float* __restrict__ sStage) {
    {
        int tid = threadIdx.x, w = tid >> 5, lane = tid & 31;
        int j0 = (tid >> 4) << 2;        // 0..124
        int t0 = (tid & 15) << 2;        // 0..60
        int jbase = w << 3;              // warp rows 8w..8w+7
        int lr0 = ((tid >> 4) & 1) << 2; // local row 0 or 4 within warp slice
        float* SW = sStage + w * 384;    // 2 stages x 192 floats
        u32 swB = (u32)__cvta_generic_to_shared(SW);

        u64 aK[4][2], aQ[4][2], aV[4][2];
        #pragma unroll
        for (int r = 0; r < 4; r++) {
            aK[r][0] = aK[r][1] = 0ull;
            aQ[r][0] = aQ[r][1] = 0ull;
            aV[r][0] = aV[r][1] = 0ull;
        }
        kqv_issue(Wk, Wq, Wv, jbase, 0, swB, lane);
        CP_COMMIT();
        #pragma unroll 1
        for (int c = 0; c < 16; c++) {
            if (c < 15) {
                kqv_issue(Wk, Wq, Wv, jbase, (c + 1) * 8, swB + ((c + 1) & 1) * 768, lane);
                CP_COMMIT();
                CP_WAIT1();
            } else {
                CP_WAIT0();
            }
            __syncwarp();
            const float* S = SW + (c & 1) * 192;
            #pragma unroll
            for (int kk = 0; kk < 8; kk += 4) {
                int k = c * 8 + kk;
                ulonglong2 b0 = *(const ulonglong2*)(sY + (k + 0) * SP + t0);
                ulonglong2 b1 = *(const ulonglong2*)(sY + (k + 1) * SP + t0);
                ulonglong2 b2 = *(const ulonglong2*)(sY + (k + 2) * SP + t0);
                ulonglong2 b3 = *(const ulonglong2*)(sY + (k + 3) * SP + t0);
                #pragma unroll
                for (int r = 0; r < 4; r++) {
                    float4 ak = *(const float4*)(S +   0 + (lr0 + r) * 8 + kk);
                    ACC_MAT(ak, b0, b1, b2, b3, aK[r]);
                    float4 aq = *(const float4*)(S +  64 + (lr0 + r) * 8 + kk);
                    ACC_MAT(aq, b0, b1, b2, b3, aQ[r]);
                    float4 av = *(const float4*)(S + 128 + (lr0 + r) * 8 + kk);
                    ACC_MAT(av, b0, b1, b2, b3, aV[r]);
                }
            }
        }
        #pragma unroll
        for (int r = 0; r < 4; r++) {
            ulonglong2 o;
            o.x = aK[r][0]; o.y = aK[r][1]; *(ulonglong2*)(sK + (j0 + r) * SP + t0) = o;
            o.x = aQ[r][0]; o.y = aQ[r][1]; *(ulonglong2*)(sQ + (j0 + r) * SP + t0) = o;
        }
        // V transposed store
        float av4[4][4];
        #pragma unroll
        for (int r = 0; r < 4; r++) {
            float2 lo = unpack2(aV[r][0]), hi = unpack2(aV[r][1]);
            av4[r][0] = lo.x; av4[r][1] = lo.y; av4[r][2] = hi.x; av4[r][3] = hi.y;
        }
        #pragma unroll
        for (int tt = 0; tt < 4; tt++) {
            float4 cc; cc.x = av4[0][tt]; cc.y = av4[1][tt]; cc.z = av4[2][tt]; cc.w = av4[3][tt];
            *(float4*)(sVt + (t0 + tt) * VTS + j0) = cc;
        }
    }
    // tail: t = 64; Vt pad rows zeroed (weights via LDG, small)
    if (threadIdx.x < HH) {
        int j = threadIdx.x;
        float cK = 0.f, cQ = 0.f, cV = 0.f;
        #pragma unroll 4
        for (int k = 0; k < HH; k += 4) {
            float y0 = sY[(k + 0) * SP + 64];
            float y1 = sY[(k + 1) * SP + 64];
            float y2 = sY[(k + 2) * SP + 64];
            float y3 = sY[(k + 3) * SP + 64];
            float4 wk4 = *(const float4*)(Wk + j * HH + k);
            cK = fmaf(wk4.x, y0, cK); cK = fmaf(wk4.y, y1, cK);
            cK = fmaf(wk4.z, y2, cK); cK = fmaf(wk4.w, y3, cK);
            float4 wq4 = *(const float4*)(Wq + j * HH + k);
            cQ = fmaf(wq4.x, y0, cQ); cQ = fmaf(wq4.y, y1, cQ);
            cQ = fmaf(wq4.z, y2, cQ); cQ = fmaf(wq4.w, y3, cQ);
            float4 wv4 = *(const float4*)(Wv + j * HH + k);
            cV = fmaf(wv4.x, y0, cV); cV = fmaf(wv4.y, y1, cV);
            cV = fmaf(wv4.z, y2, cV); cV = fmaf(wv4.w, y3, cV);
        }
        sK[j * SP + 64] = cK;
        sQ[j * SP + 64] = cQ;
        sVt[64 * VTS + j] = cV;
        sVt[65 * VTS + j] = 0.f;
        sVt[66 * VTS + j] = 0.f;
        sVt[67 * VTS + j] = 0.f;
    }
}

// Fused 2-matrix projection (layer-2 q2 both heads), staged weights.
__device__ __forceinline__ void gemm_KQ2(
    const float* __restrict__ Wa, const float* __restrict__ Wb,
    const float* __restrict__ sY,
    float* __restrict__ sA, float* __restrict__ sB2,
    float* __restrict__ sStage) {
    {
        int tid = threadIdx.x, w = tid >> 5, lane = tid & 31;
        int j0 = (tid >> 4) << 2;
        int t0 = (tid & 15) << 2;
        int jbase = w << 3;
        int lr0 = ((tid >> 4) & 1) << 2;
        float* SW = sStage + w * 256;    // 2 stages x 128 floats
        u32 swB = (u32)__cvta_generic_to_shared(SW);

        u64 aA[4][2], aB[4][2];
        #pragma unroll
        for (int r = 0; r < 4; r++) {
            aA[r][0] = aA[r][1] = 0ull;
            aB[r][0] = aB[r][1] = 0ull;
        }
        kq2_issue(Wa, Wb, jbase, 0, swB, lane);
        CP_COMMIT();
        #pragma unroll 1
        for (int c = 0; c < 16; c++) {
            if (c < 15) {
                kq2_issue(Wa, Wb, jbase, (c + 1) * 8, swB + ((c + 1) & 1) * 512, lane);
                CP_COMMIT();
                CP_WAIT1();
            } else {
                CP_WAIT0();
            }
            __syncwarp();
            const float* S = SW + (c & 1) * 128;
            #pragma unroll
            for (int kk = 0; kk < 8; kk += 4) {
                int k = c * 8 + kk;
                ulonglong2 b0 = *(const ulonglong2*)(sY + (k + 0) * SP + t0);
                ulonglong2 b1 = *(const ulonglong2*)(sY + (k + 1) * SP + t0);
                ulonglong2 b2 = *(const ulonglong2*)(sY + (k + 2) * SP + t0);
                ulonglong2 b3 = *(const ulonglong2*)(sY + (k + 3) * SP + t0);
                #pragma unroll
                for (int r = 0; r < 4; r++) {
                    float4 wa = *(const float4*)(S +  0 + (lr0 + r) * 8 + kk);
                    ACC_MAT(wa, b0, b1, b2, b3, aA[r]);
                    float4 wb = *(const float4*)(S + 64 + (lr0 + r) * 8 + kk);
                    ACC_MAT(wb, b0, b1, b2, b3, aB[r]);
                }
            }
        }
        #pragma unroll
        for (int r = 0; r < 4; r++) {
            ulonglong2 o;
            o.x = aA[r][0]; o.y = aA[r][1]; *(ulonglong2*)(sA  + (j0 + r) * SP + t0) = o;
            o.x = aB[r][0]; o.y = aB[r][1]; *(ulonglong2*)(sB2 + (j0 + r) * SP + t0) = o;
        }
    }
    if (threadIdx.x < HH) {
        int j = threadIdx.x;
        float cA = 0.f, cB = 0.f;
        #pragma unroll 4
        for (int k = 0; k < HH; k += 4) {
            float y0 = sY[(k + 0) * SP + 64];
            float y1 = sY[(k + 1) * SP + 64];
            float y2 = sY[(k + 2) * SP + 64];
            float y3 = sY[(k + 3) * SP + 64];
            float4 wa4 = *(const float4*)(Wa + j * HH + k);
            cA = fmaf(wa4.x, y0, cA); cA = fmaf(wa4.y, y1, cA);
            cA = fmaf(wa4.z, y2, cA); cA = fmaf(wa4.w, y3, cA);
            float4 wb4 = *(const float4*)(Wb + j * HH + k);
            cB = fmaf(wb4.x, y0, cB); cB = fmaf(wb4.y, y1, cB);
            cB = fmaf(wb4.z, y2, cB); cB = fmaf(wb4.w, y3, cB);
        }
        sA[j * SP + 64]  = cA;
        sB2[j * SP + 64] = cB;
    }
}

// Row-wise softmax on one row (65 real cols), warp-collective. Zeroes pads.
__device__ __forceinline__ void softmax_row(float* __restrict__ row, int lane) {
    float v0 = row[lane], v1 = row[lane + 32], v2 = row[64];
    float m = fmaxf(fmaxf(v0, v1), v2);
    #pragma unroll
    for (int o = 16; o; o >>= 1) m = fmaxf(m, __shfl_xor_sync(0xffffffffu, m, o));
    float e0 = expf(v0 - m), e1 = expf(v1 - m), e2 = expf(v2 - m);
    float sum = e0 + e1;
    #pragma unroll
    for (int o = 16; o; o >>= 1) sum += __shfl_xor_sync(0xffffffffu, sum, o);
    float denom = sum + e2;
    row[lane] = e0 / denom;
    row[lane + 32] = e1 / denom;
    if (lane == 0) { row[64] = e2 / denom; row[65] = 0.f; row[66] = 0.f; row[67] = 0.f; }
}

// Fused kq -> softmax -> O, barrier-free (warp row-ownership; 16 warps).
// warp w owns rows 4w..4w+3; warp 0 additionally owns row 64 end-to-end.
__device__ __forceinline__ void attn_fused(const float* __restrict__ sK,
                                           const float* __restrict__ sQ,
                                           const float* __restrict__ sVt,
                                           float* __restrict__ sKQ,
                                           float* __restrict__ sO) {
    int tid = threadIdx.x, w = tid >> 5, lane = tid & 31;
    int s0 = w << 2, t2 = lane << 1;

    // ---- kq main: rows s0..s0+3, cols t2, t2+1 (chain i ascending)
    {
        u64 a0 = 0ull, a1 = 0ull, a2 = 0ull, a3 = 0ull;
        #pragma unroll 4
        for (int i = 0; i < HH; i++) {
            float4 kv = *(const float4*)(sK + i * SP + s0);
            u64 q = *(const u64*)(sQ + i * SP + t2);
            a0 = fma2(pack2(kv.x, kv.x), q, a0);
            a1 = fma2(pack2(kv.y, kv.y), q, a1);
            a2 = fma2(pack2(kv.z, kv.z), q, a2);
            a3 = fma2(pack2(kv.w, kv.w), q, a3);
        }
        *(u64*)(sKQ + (s0 + 0) * SP + t2) = a0;
        *(u64*)(sKQ + (s0 + 1) * SP + t2) = a1;
        *(u64*)(sKQ + (s0 + 2) * SP + t2) = a2;
        *(u64*)(sKQ + (s0 + 3) * SP + t2) = a3;
    }
    // col 64 for own rows (lanes 0..3, scalar in-order)
    if (lane < 4) {
        int s = s0 + lane;
        float acc = 0.f;
        #pragma unroll 8
        for (int i = 0; i < HH; i++)
            acc = fmaf(sK[i * SP + s], sQ[i * SP + 64], acc);
        sKQ[s * SP + 64] = acc;
    }
    // row 64 (warp 0): packed pairs per lane + corner by lane 0
    if (w == 0) {
        u64 acc = 0ull;
        #pragma unroll 8
        for (int i = 0; i < HH; i++) {
            float kk = sK[i * SP + 64];
            acc = fma2(pack2(kk, kk), *(const u64*)(sQ + i * SP + t2), acc);
        }
        *(u64*)(sKQ + 64 * SP + t2) = acc;
        if (lane == 0) {
            float a = 0.f;
            #pragma unroll 8
            for (int i = 0; i < HH; i++)
                a = fmaf(sK[i * SP + 64], sQ[i * SP + 64], a);
            sKQ[64 * SP + 64] = a;
        }
    }
    __syncwarp();

    // ---- softmax on own rows
    #pragma unroll
    for (int r = 0; r < 4; r++) softmax_row(sKQ + (s0 + r) * SP, lane);
    if (w == 0) softmax_row(sKQ + 64 * SP, lane);
    __syncwarp();

    // ---- O: rows s0..s0+3, i0 = lane*4, packed over i-pairs, chain t ascending
    {
        int i0 = lane << 2;
        u64 o[4][2];
        #pragma unroll
        for (int r = 0; r < 4; r++) { o[r][0] = 0ull; o[r][1] = 0ull; }
        #pragma unroll 1
        for (int tb = 0; tb < SP; tb += 4) {
            float4 q0 = *(const float4*)(sKQ + (s0 + 0) * SP + tb);
            float4 q1 = *(const float4*)(sKQ + (s0 + 1) * SP + tb);
            float4 q2v = *(const float4*)(sKQ + (s0 + 2) * SP + tb);
            float4 q3 = *(const float4*)(sKQ + (s0 + 3) * SP + tb);
            float p0[4] = {q0.x, q0.y, q0.z, q0.w};
            float p1[4] = {q1.x, q1.y, q1.z, q1.w};
            float p2[4] = {q2v.x, q2v.y, q2v.z, q2v.w};
            float p3[4] = {q3.x, q3.y, q3.z, q3.w};
            #pragma unroll
            for (int tt = 0; tt < 4; tt++) {
                ulonglong2 vv = *(const ulonglong2*)(sVt + (tb + tt) * VTS + i0);
                u64 pp;
                pp = pack2(p0[tt], p0[tt]); o[0][0] = fma2(pp, vv.x, o[0][0]); o[0][1] = fma2(pp, vv.y, o[0][1]);
                pp = pack2(p1[tt], p1[tt]); o[1][0] = fma2(pp, vv.x, o[1][0]); o[1][1] = fma2(pp, vv.y, o[1][1]);
                pp = pack2(p2[tt], p2[tt]); o[2][0] = fma2(pp, vv.x, o[2][0]); o[2][1] = fma2(pp, vv.y, o[2][1]);
                pp = pack2(p3[tt], p3[tt]); o[3][0] = fma2(pp, vv.x, o[3][0]); o[3][1] = fma2(pp, vv.y, o[3][1]);
            }
        }
        #pragma unroll
        for (int r = 0; r < 4; r++) {
            ulonglong2 ov; ov.x = o[r][0]; ov.y = o[r][1];
            *(ulonglong2*)(sO + (s0 + r) * HH + i0) = ov;
        }
        // row 64 (warp 0)
        if (w == 0) {
            u64 oa = 0ull, ob = 0ull;
            #pragma unroll 1
            for (int tb = 0; tb < SP; tb += 4) {
                float4 q = *(const float4*)(sKQ + 64 * SP + tb);
                float pr[4] = {q.x, q.y, q.z, q.w};
                #pragma unroll
                for (int tt = 0; tt < 4; tt++) {
                    ulonglong2 vv = *(const ulonglong2*)(sVt + (tb + tt) * VTS + i0);
                    u64 pp = pack2(pr[tt], pr[tt]);
                    oa = fma2(pp, vv.x, oa);
                    ob = fma2(pp, vv.y, ob);
                }
            }
            ulonglong2 o64; o64.x = oa; o64.y = ob;
            *(ulonglong2*)(sO + 64 * HH + i0) = o64;
        }
    }
}

// sZ[s*HH + j] (FIRST: =, else continue chain) sum_i sO[s*HH+i] * L[i*HH+j]
template <int FIRST>
__device__ __forceinline__ void gemm_Z(const float* __restrict__ sO,
                                       const float* __restrict__ L,
                                       float* __restrict__ sZ) {
    {
        int tid = threadIdx.x;
        int s0 = (tid >> 5) << 2;        // 0..60
        int j0 = (tid & 31) << 2;        // 0..124
        u64 acc[4][2];
        #pragma unroll
        for (int r = 0; r < 4; r++) {
            if (FIRST) { acc[r][0] = 0ull; acc[r][1] = 0ull; }
            else {
                ulonglong2 z = *(const ulonglong2*)(sZ + (s0 + r) * HH + j0);
                acc[r][0] = z.x; acc[r][1] = z.y;
            }
        }
        #pragma unroll 1
        for (int i = 0; i < HH; i += 4) {
            if (i + 16 < HH) {
                PF_L1(L + (i + 16) * HH + j0);
                PF_L1(L + (i + 17) * HH + j0);
                PF_L1(L + (i + 18) * HH + j0);
                PF_L1(L + (i + 19) * HH + j0);
            }
            ulonglong2 l0 = *(const ulonglong2*)(L + (i + 0) * HH + j0);
            ulonglong2 l1 = *(const ulonglong2*)(L + (i + 1) * HH + j0);
            ulonglong2 l2 = *(const ulonglong2*)(L + (i + 2) * HH + j0);
            ulonglong2 l3 = *(const ulonglong2*)(L + (i + 3) * HH + j0);
            #pragma unroll
            for (int r = 0; r < 4; r++) {
                float4 o = *(const float4*)(sO + (s0 + r) * HH + i);
                ACC_MAT(o, l0, l1, l2, l3, acc[r]);
            }
        }
        #pragma unroll
        for (int r = 0; r < 4; r++) {
            ulonglong2 o; o.x = acc[r][0]; o.y = acc[r][1];
            *(ulonglong2*)(sZ + (s0 + r) * HH + j0) = o;
        }
    }
    // tail: s = 64 (same tid -> same element across FIRST/continue, no sync needed)
    if (threadIdx.x < HH) {
        int j = threadIdx.x;
        float acc = FIRST ? 0.f : sZ[64 * HH + j];
        #pragma unroll 8
        for (int i = 0; i < HH; i++)
            acc = fmaf(sO[64 * HH + i], L[i * HH + j], acc);
        sZ[64 * HH + j] = acc;
    }
}

// smem layout (floats):
//  P0 @     0 : 8704  Y -> O1 (stride 128)
//  P1 @  8704 : 8704  K0 -> K1 -> Z (stride 128)
//  P2 @ 17408 : 8704  Q0 -> Q1 -> Y2
//  P3 @ 26112 : 8976  V0t -> V1t -> q2a
//  P4 @ 35088 : 8704  O0 -> q2b
//  KQ @ 43792 : 4624
//  EX @ 48416 : 1120
//  ST @ 49536 : 6144  per-warp cp.async weight staging (16 x 384)
#define SMEM_FLOATS 55680

__global__ void __launch_bounds__(NT, 1) board_kernel(
    const float* __restrict__ inp, const float* __restrict__ emb,
    const float* __restrict__ wk11, const float* __restrict__ wq11, const float* __restrict__ wv11,
    const float* __restrict__ wk12, const float* __restrict__ wq12, const float* __restrict__ wv12,
    const float* __restrict__ L1,
    const float* __restrict__ wk21, const float* __restrict__ wq21, const float* __restrict__ wv21,
    const float* __restrict__ wk22, const float* __restrict__ wq22, const float* __restrict__ wv22,
    const float* __restrict__ L2, const float* __restrict__ L3, const float* __restrict__ L4,
    float* __restrict__ out) {
    extern __shared__ float sm[];
    float* P0  = sm;
    float* P1  = sm + 8704;
    float* P2  = sm + 17408;
    float* P3  = sm + 26112;
    float* P4  = sm + 35088;
    float* sKQ = sm + 43792;
    float* sEX = sm + 48416;
    float* sST = sm + 49536;

    float* sc   = sEX;          // 2 x 128
    float* sw   = sEX + 256;    // 2 x 72 (stride 72)
    float* syw  = sEX + 416;    // 2 x 128
    float* satt = sEX + 672;    // 256
    float* sh2  = sEX + 928;    // 128
    float* sh3  = sEX + 1056;   // 64

    const int b = blockIdx.x;
    const int tid = threadIdx.x;
    const float* x = inp + (size_t)b * 64;

    // Y[j][s] = emb[j][s] * x[s], x[64]=1; padding cols zero.
    for (int idx = tid; idx < HH * SP; idx += NT) {
        int j = idx / SP, s = idx - j * SP;
        float v = 0.f;
        if (s < 64)       v = emb[j * 65 + s] * x[s];
        else if (s == 64) v = emb[j * 65 + 64];
        P0[idx] = v;
    }
    __syncthreads();

    // ---- layer 1, head 0 ----
    gemm_KQV(wk11, wq11, wv11, P0, P1, P2, P3, sST);   // K0, Q0, V0t
    __syncthreads();
    attn_fused(P1, P2, P3, sKQ, P4);                   // O0 -> P4
    __syncthreads();

    // ---- layer 1, head 1 ----
    gemm_KQV(wk12, wq12, wv12, P0, P1, P2, P3, sST);   // K1, Q1, V1t
    __syncthreads();
    attn_fused(P1, P2, P3, sKQ, P0);                   // O1 -> P0 (Y dead)
    __syncthreads();

    // Z = O0 @ L1[:128] then += O1 @ L1[128:] (single 256-deep in-order chain)
    gemm_Z<1>(P4, L1,           P1);
    gemm_Z<0>(P0, L1 + HH * HH, P1);                   // row-ownership identical: no sync
    __syncthreads();

    // tanh + transpose: Y2[j][s] = tanh(Z[s][j]) -> P2
    for (int idx = tid; idx < HH * SP; idx += NT) {
        int j = idx / SP, s = idx - j * SP;
        P2[idx] = (s < SS) ? tanhf(P1[s * HH + j]) : 0.f;
    }
    __syncthreads();

    // ---- layer 2: both heads merged ----
    if (tid < 2 * HH) {                           // c[h][i] = Wk2h[i,:] . y64 (in-order)
        int h = tid >> 7, i = tid & 127;
        const float* Wk = h ? wk22 : wk21;
        float acc = 0.f;
        #pragma unroll 8
        for (int j = 0; j < HH; j++)
            acc = fmaf(Wk[i * HH + j], P2[j * SP + 64], acc);
        sc[(h << 7) + i] = acc;
    }
    gemm_KQ2(wq21, wq22, P2, P3, P4, sST);        // q2a -> P3, q2b -> P4
    __syncthreads();

    if (tid < 2 * SS) {                           // logits[h][t] = c[h] . q2h[:,t]
        int h = tid >= SS, t = tid - (h ? SS : 0);
        const float* q2 = h ? P4 : P3;
        const float* ch = sc + (h << 7);
        float acc = 0.f;
        #pragma unroll 8
        for (int i = 0; i < HH; i++)
            acc = fmaf(ch[i], q2[i * SP + t], acc);
        sw[h * 72 + t] = acc;
    }
    __syncthreads();
    if (tid < 64) {                               // softmax rows (warps 0,1)
        int h = tid >> 5, lane = tid & 31;
        softmax_row(sw + h * 72, lane);
    }
    __syncthreads();
    if (tid < 2 * HH) {                           // yw[h][j] = sum_t w[h][t] * Y2[j][t]
        int h = tid >> 7, j = tid & 127;
        const float* wrow = sw + h * 72;
        float acc = 0.f;
        #pragma unroll
        for (int t = 0; t < SP; t += 4) {
            float4 y4 = *(const float4*)(P2 + j * SP + t);
            float4 w4 = *(const float4*)(wrow + t);
            acc = dot4(y4, w4, acc);
        }
        syw[(h << 7) + j] = acc;
    }
    __syncthreads();
    if (tid < 2 * HH) {                           // att[h][i] = Wv2h[i,:] . yw[h]
        int h = tid >> 7, i = tid & 127;
        const float* Wv = h ? wv22 : wv21;
        const float* yh = syw + (h << 7);
        float acc = 0.f;
        #pragma unroll 8
        for (int j = 0; j < HH; j += 4) {
            float4 w4 = *(const float4*)(Wv + i * HH + j);
            float4 y4 = *(const float4*)(yh + j);
            acc = dot4(w4, y4, acc);
        }
        satt[(h << 7) + i] = acc;
    }
    __syncthreads();

    // head: h2 = tanh(cat(att) @ L2), h3 = tanh(h2 @ L3), score = h3 @ L4
    if (tid < HH) {
        float acc = 0.f;
        #pragma unroll 8
        for (int i = 0; i < 2 * HH; i++)
            acc = fmaf(satt[i], L2[i * HH + tid], acc);
        sh2[tid] = tanhf(acc);
    }
    __syncthreads();
    if (tid < 64) {
        float acc = 0.f;
        #pragma unroll 8
        for (int j = 0; j < HH; j++)
            acc = fmaf(sh2[j], L3[j * 64 + tid], acc);
        sh3[tid] = tanhf(acc);
    }
    __syncthreads();
    if (tid == 0) {
        float acc = 0.f;
        #pragma unroll
        for (int m = 0; m < 64; m++) acc = fmaf(sh3[m], L4[m], acc);
        out[b] = acc;
    }
}

extern "C" void kernel_launch(void* const* d_in, const int* in_sizes, int n_in,
                              void* d_out, int out_size) {
    const float* inputs = (const float*)d_in[0];
    const float* emb    = (const float*)d_in[1];
    const float* wk11   = (const float*)d_in[2];
    const float* wq11   = (const float*)d_in[3];
    const float* wv11   = (const float*)d_in[4];
    const float* wk12   = (const float*)d_in[5];
    const float* wq12   = (const float*)d_in[6];
    const float* wv12   = (const float*)d_in[7];
    const float* L1     = (const float*)d_in[8];
    const float* wk21   = (const float*)d_in[9];
    const float* wq21   = (const float*)d_in[10];
    const float* wv21   = (const float*)d_in[11];
    const float* wk22   = (const float*)d_in[12];
    const float* wq22   = (const float*)d_in[13];
    const float* wv22   = (const float*)d_in[14];
    const float* L2     = (const float*)d_in[15];
    const float* L3     = (const float*)d_in[16];
    const float* L4     = (const float*)d_in[17];
    (void)n_in; (void)in_sizes;

    int B = out_size;  // one score per board (8192)

    size_t smem = SMEM_FLOATS * sizeof(float);
    cudaFuncSetAttribute(board_kernel, cudaFuncAttributeMaxDynamicSharedMemorySize, (int)smem);

    board_kernel<<<B, NT, smem>>>(inputs, emb,
                                  wk11, wq11, wv11, wk12, wq12, wv12, L1,
                                  wk21, wq21, wv21, wk22, wq22, wv22, L2, L3, L4,
                                  (float*)d_out);
}

// round 13
// speedup vs baseline: 1.2515x; 1.0264x over previous
#include <cuda_runtime.h>
#include <math.h>

#define HH 128
#define SS 65
#define SP 68          // padded S stride (cols 65..67 zero where read)
#define VTS 132        // transposed-V stride
#define NT 512

typedef unsigned long long u64;
typedef unsigned int u32;

__device__ __forceinline__ u64 pack2(float lo, float hi) {
    u64 r; asm("mov.b64 %0, {%1, %2};" : "=l"(r) : "f"(lo), "f"(hi)); return r;
}
__device__ __forceinline__ float2 unpack2(u64 p) {
    float2 v; asm("mov.b64 {%0, %1}, %2;" : "=f"(v.x), "=f"(v.y) : "l"(p)); return v;
}
__device__ __forceinline__ u64 fma2(u64 a, u64 b, u64 c) {
    u64 d; asm("fma.rn.f32x2 %0, %1, %2, %3;" : "=l"(d) : "l"(a), "l"(b), "l"(c)); return d;
}
__device__ __forceinline__ float dot4(const float4& a, const float4& b, float acc) {
    acc = fmaf(a.x, b.x, acc);
    acc = fmaf(a.y, b.y, acc);
    acc = fmaf(a.z, b.z, acc);
    acc = fmaf(a.w, b.w, acc);
    return acc;
}

__device__ __forceinline__ void cp16(u32 saddr, const float* g) {
    asm volatile("cp.async.cg.shared.global [%0], [%1], 16;" :: "r"(saddr), "l"(g));
}
#define CP_COMMIT() asm volatile("cp.async.commit_group;" ::: "memory")
#define CP_WAIT1()  asm volatile("cp.async.wait_group 1;" ::: "memory")
#define CP_WAIT0()  asm volatile("cp.async.wait_group 0;" ::: "memory")

#define ACC_MAT(AR, Bx, By, Bz, Bw, ACC)                                              \
    do {                                                                              \
        u64 p_;                                                                       \
        p_ = pack2(AR.x, AR.x); ACC[0] = fma2(p_, Bx.x, ACC[0]); ACC[1] = fma2(p_, Bx.y, ACC[1]); \
        p_ = pack2(AR.y, AR.y); ACC[0] = fma2(p_, By.x, ACC[0]); ACC[1] = fma2(p_, By.y, ACC[1]); \
        p_ = pack2(AR.z, AR.z); ACC[0] = fma2(p_, Bz.x, ACC[0]); ACC[1] = fma2(p_, Bz.y, ACC[1]); \
        p_ = pack2(AR.w, AR.w); ACC[0] = fma2(p_, Bw.x, ACC[0]); ACC[1] = fma2(p_, Bw.y, ACC[1]); \
    } while (0)

// ---- per-warp cp.async staging loaders (no barriers: each warp reads only its slice) ----
// KQV chunk: [3 mats][8 rows][8 k] floats = 192 floats = 48 float4 per stage.
__device__ __forceinline__ void kqv_issue(const float* __restrict__ Wk,
                                          const float* __restrict__ Wq,
                                          const float* __restrict__ Wv,
                                          int jbase, int k0, u32 dstB, int lane) {
    {
        int m = lane >> 4, sub = lane & 15, row = sub >> 1, half = sub & 1;
        const float* W = (m == 0) ? Wk : Wq;
        cp16(dstB + ((m * 64 + row * 8 + half * 4) << 2),
             W + (jbase + row) * HH + k0 + half * 4);
    }
    if (lane < 16) {
        int sub = lane;
        int row = sub >> 1, half = sub & 1;
        cp16(dstB + ((2 * 64 + row * 8 + half * 4) << 2),
             Wv + (jbase + row) * HH + k0 + half * 4);
    }
}
// KQ2 chunk: [2 mats][8 rows][8 k] = 128 floats = 32 float4 per stage.
__device__ __forceinline__ void kq2_issue(const float* __restrict__ Wa,
                                          const float* __restrict__ Wb,
                                          int jbase, int k0, u32 dstB, int lane) {
    int m = lane >> 4, sub = lane & 15, row = sub >> 1, half = sub & 1;
    const float* W = (m == 0) ? Wa : Wb;
    cp16(dstB + ((m * 64 + row * 8 + half * 4) << 2),
         W + (jbase + row) * HH + k0 + half * 4);
}

// Fused K/Q/V projection, one Y sweep, weights staged smem<-L2 via per-warp cp.async.
// Tiles (round-8 mapping): j0=(tid>>4)<<2, t0=(tid&15)<<2. Chains: k ascending (bit-identical).
__device__ __forceinline__ void gemm_KQV(
    const float* __restrict__ Wk, const float* __restrict__ Wq, const float* __restrict__ Wv,
    const float* __restrict__ sY,
    float* __restrict__ sK, float* __restrict__ sQ, float* __restrict__ sVt,
    float* __restrict__ sStage) {
    {
        int tid = threadIdx.x, w = tid >> 5, lane = tid & 31;
        int j0 = (tid >> 4) << 2;        // 0..124
        int t0 = (tid & 15) << 2;        // 0..60
        int jbase = w << 3;              // warp rows 8w..8w+7
        int lr0 = ((tid >> 4) & 1) << 2; // local row 0 or 4 within warp slice
        float* SW = sStage + w * 384;    // 2 stages x 192 floats
        u32 swB = (u32)__cvta_generic_to_shared(SW);

        u64 aK[4][2], aQ[4][2], aV[4][2];
        #pragma unroll
        for (int r = 0; r < 4; r++) {
            aK[r][0] = aK[r][1] = 0ull;
            aQ[r][0] = aQ[r][1] = 0ull;
            aV[r][0] = aV[r][1] = 0ull;
        }
        kqv_issue(Wk, Wq, Wv, jbase, 0, swB, lane);
        CP_COMMIT();
        #pragma unroll 1
        for (int c = 0; c < 16; c++) {
            if (c < 15) {
                kqv_issue(Wk, Wq, Wv, jbase, (c + 1) * 8, swB + ((c + 1) & 1) * 768, lane);
                CP_COMMIT();
                CP_WAIT1();
            } else {
                CP_WAIT0();
            }
            __syncwarp();
            const float* S = SW + (c & 1) * 192;
            #pragma unroll
            for (int kk = 0; kk < 8; kk += 4) {
                int k = c * 8 + kk;
                ulonglong2 b0 = *(const ulonglong2*)(sY + (k + 0) * SP + t0);
                ulonglong2 b1 = *(const ulonglong2*)(sY + (k + 1) * SP + t0);
                ulonglong2 b2 = *(const ulonglong2*)(sY + (k + 2) * SP + t0);
                ulonglong2 b3 = *(const ulonglong2*)(sY + (k + 3) * SP + t0);
                #pragma unroll
                for (int r = 0; r < 4; r++) {
                    float4 ak = *(const float4*)(S +   0 + (lr0 + r) * 8 + kk);
                    ACC_MAT(ak, b0, b1, b2, b3, aK[r]);
                    float4 aq = *(const float4*)(S +  64 + (lr0 + r) * 8 + kk);
                    ACC_MAT(aq, b0, b1, b2, b3, aQ[r]);
                    float4 av = *(const float4*)(S + 128 + (lr0 + r) * 8 + kk);
                    ACC_MAT(av, b0, b1, b2, b3, aV[r]);
                }
            }
        }
        #pragma unroll
        for (int r = 0; r < 4; r++) {
            ulonglong2 o;
            o.x = aK[r][0]; o.y = aK[r][1]; *(ulonglong2*)(sK + (j0 + r) * SP + t0) = o;
            o.x = aQ[r][0]; o.y = aQ[r][1]; *(ulonglong2*)(sQ + (j0 + r) * SP + t0) = o;
        }
        // V transposed store
        float av4[4][4];
        #pragma unroll
        for (int r = 0; r < 4; r++) {
            float2 lo = unpack2(aV[r][0]), hi = unpack2(aV[r][1]);
            av4[r][0] = lo.x; av4[r][1] = lo.y; av4[r][2] = hi.x; av4[r][3] = hi.y;
        }
        #pragma unroll
        for (int tt = 0; tt < 4; tt++) {
            float4 cc; cc.x = av4[0][tt]; cc.y = av4[1][tt]; cc.z = av4[2][tt]; cc.w = av4[3][tt];
            *(float4*)(sVt + (t0 + tt) * VTS + j0) = cc;
        }
    }
    // tail: t = 64; Vt pad rows zeroed (weights via LDG, small)
    if (threadIdx.x < HH) {
        int j = threadIdx.x;
        float cK = 0.f, cQ = 0.f, cV = 0.f;
        #pragma unroll 4
        for (int k = 0; k < HH; k += 4) {
            float y0 = sY[(k + 0) * SP + 64];
            float y1 = sY[(k + 1) * SP + 64];
            float y2 = sY[(k + 2) * SP + 64];
            float y3 = sY[(k + 3) * SP + 64];
            float4 wk4 = *(const float4*)(Wk + j * HH + k);
            cK = fmaf(wk4.x, y0, cK); cK = fmaf(wk4.y, y1, cK);
            cK = fmaf(wk4.z, y2, cK); cK = fmaf(wk4.w, y3, cK);
            float4 wq4 = *(const float4*)(Wq + j * HH + k);
            cQ = fmaf(wq4.x, y0, cQ); cQ = fmaf(wq4.y, y1, cQ);
            cQ = fmaf(wq4.z, y2, cQ); cQ = fmaf(wq4.w, y3, cQ);
            float4 wv4 = *(const float4*)(Wv + j * HH + k);
            cV = fmaf(wv4.x, y0, cV); cV = fmaf(wv4.y, y1, cV);
            cV = fmaf(wv4.z, y2, cV); cV = fmaf(wv4.w, y3, cV);
        }
        sK[j * SP + 64] = cK;
        sQ[j * SP + 64] = cQ;
        sVt[64 * VTS + j] = cV;
        sVt[65 * VTS + j] = 0.f;
        sVt[66 * VTS + j] = 0.f;
        sVt[67 * VTS + j] = 0.f;
    }
}

// Fused 2-matrix projection (layer-2 q2 both heads), staged weights.
__device__ __forceinline__ void gemm_KQ2(
    const float* __restrict__ Wa, const float* __restrict__ Wb,
    const float* __restrict__ sY,
    float* __restrict__ sA, float* __restrict__ sB2,
    float* __restrict__ sStage) {
    {
        int tid = threadIdx.x, w = tid >> 5, lane = tid & 31;
        int j0 = (tid >> 4) << 2;
        int t0 = (tid & 15) << 2;
        int jbase = w << 3;
        int lr0 = ((tid >> 4) & 1) << 2;
        float* SW = sStage + w * 256;    // 2 stages x 128 floats
        u32 swB = (u32)__cvta_generic_to_shared(SW);

        u64 aA[4][2], aB[4][2];
        #pragma unroll
        for (int r = 0; r < 4; r++) {
            aA[r][0] = aA[r][1] = 0ull;
            aB[r][0] = aB[r][1] = 0ull;
        }
        kq2_issue(Wa, Wb, jbase, 0, swB, lane);
        CP_COMMIT();
        #pragma unroll 1
        for (int c = 0; c < 16; c++) {
            if (c < 15) {
                kq2_issue(Wa, Wb, jbase, (c + 1) * 8, swB + ((c + 1) & 1) * 512, lane);
                CP_COMMIT();
                CP_WAIT1();
            } else {
                CP_WAIT0();
            }
            __syncwarp();
            const float* S = SW + (c & 1) * 128;
            #pragma unroll
            for (int kk = 0; kk < 8; kk += 4) {
                int k = c * 8 + kk;
                ulonglong2 b0 = *(const ulonglong2*)(sY + (k + 0) * SP + t0);
                ulonglong2 b1 = *(const ulonglong2*)(sY + (k + 1) * SP + t0);
                ulonglong2 b2 = *(const ulonglong2*)(sY + (k + 2) * SP + t0);
                ulonglong2 b3 = *(const ulonglong2*)(sY + (k + 3) * SP + t0);
                #pragma unroll
                for (int r = 0; r < 4; r++) {
                    float4 wa = *(const float4*)(S +  0 + (lr0 + r) * 8 + kk);
                    ACC_MAT(wa, b0, b1, b2, b3, aA[r]);
                    float4 wb = *(const float4*)(S + 64 + (lr0 + r) * 8 + kk);
                    ACC_MAT(wb, b0, b1, b2, b3, aB[r]);
                }
            }
        }
        #pragma unroll
        for (int r = 0; r < 4; r++) {
            ulonglong2 o;
            o.x = aA[r][0]; o.y = aA[r][1]; *(ulonglong2*)(sA  + (j0 + r) * SP + t0) = o;
            o.x = aB[r][0]; o.y = aB[r][1]; *(ulonglong2*)(sB2 + (j0 + r) * SP + t0) = o;
        }
    }
    if (threadIdx.x < HH) {
        int j = threadIdx.x;
        float cA = 0.f, cB = 0.f;
        #pragma unroll 4
        for (int k = 0; k < HH; k += 4) {
            float y0 = sY[(k + 0) * SP + 64];
            float y1 = sY[(k + 1) * SP + 64];
            float y2 = sY[(k + 2) * SP + 64];
            float y3 = sY[(k + 3) * SP + 64];
            float4 wa4 = *(const float4*)(Wa + j * HH + k);
            cA = fmaf(wa4.x, y0, cA); cA = fmaf(wa4.y, y1, cA);
            cA = fmaf(wa4.z, y2, cA); cA = fmaf(wa4.w, y3, cA);
            float4 wb4 = *(const float4*)(Wb + j * HH + k);
            cB = fmaf(wb4.x, y0, cB); cB = fmaf(wb4.y, y1, cB);
            cB = fmaf(wb4.z, y2, cB); cB = fmaf(wb4.w, y3, cB);
        }
        sA[j * SP + 64]  = cA;
        sB2[j * SP + 64] = cB;
    }
}

// Row-wise softmax on one row (65 real cols), warp-collective. Zeroes pads.
__device__ __forceinline__ void softmax_row(float* __restrict__ row, int lane) {
    float v0 = row[lane], v1 = row[lane + 32], v2 = row[64];
    float m = fmaxf(fmaxf(v0, v1), v2);
    #pragma unroll
    for (int o = 16; o; o >>= 1) m = fmaxf(m, __shfl_xor_sync(0xffffffffu, m, o));
    float e0 = expf(v0 - m), e1 = expf(v1 - m), e2 = expf(v2 - m);
    float sum = e0 + e1;
    #pragma unroll
    for (int o = 16; o; o >>= 1) sum += __shfl_xor_sync(0xffffffffu, sum, o);
    float denom = sum + e2;
    row[lane] = e0 / denom;
    row[lane + 32] = e1 / denom;
    if (lane == 0) { row[64] = e2 / denom; row[65] = 0.f; row[66] = 0.f; row[67] = 0.f; }
}

// Fused kq -> softmax -> O, barrier-free (warp row-ownership; 16 warps).
// warp w owns rows 4w..4w+3; warp 0 additionally owns row 64 end-to-end.
__device__ __forceinline__ void attn_fused(const float* __restrict__ sK,
                                           const float* __restrict__ sQ,
                                           const float* __restrict__ sVt,
                                           float* __restrict__ sKQ,
                                           float* __restrict__ sO) {
    int tid = threadIdx.x, w = tid >> 5, lane = tid & 31;
    int s0 = w << 2, t2 = lane << 1;

    // ---- kq main: rows s0..s0+3, cols t2, t2+1 (chain i ascending)
    {
        u64 a0 = 0ull, a1 = 0ull, a2 = 0ull, a3 = 0ull;
        #pragma unroll 4
        for (int i = 0; i < HH; i++) {
            float4 kv = *(const float4*)(sK + i * SP + s0);
            u64 q = *(const u64*)(sQ + i * SP + t2);
            a0 = fma2(pack2(kv.x, kv.x), q, a0);
            a1 = fma2(pack2(kv.y, kv.y), q, a1);
            a2 = fma2(pack2(kv.z, kv.z), q, a2);
            a3 = fma2(pack2(kv.w, kv.w), q, a3);
        }
        *(u64*)(sKQ + (s0 + 0) * SP + t2) = a0;
        *(u64*)(sKQ + (s0 + 1) * SP + t2) = a1;
        *(u64*)(sKQ + (s0 + 2) * SP + t2) = a2;
        *(u64*)(sKQ + (s0 + 3) * SP + t2) = a3;
    }
    // col 64 for own rows (lanes 0..3, scalar in-order)
    if (lane < 4) {
        int s = s0 + lane;
        float acc = 0.f;
        #pragma unroll 8
        for (int i = 0; i < HH; i++)
            acc = fmaf(sK[i * SP + s], sQ[i * SP + 64], acc);
        sKQ[s * SP + 64] = acc;
    }
    // row 64 (warp 0): packed pairs per lane + corner by lane 0
    if (w == 0) {
        u64 acc = 0ull;
        #pragma unroll 8
        for (int i = 0; i < HH; i++) {
            float kk = sK[i * SP + 64];
            acc = fma2(pack2(kk, kk), *(const u64*)(sQ + i * SP + t2), acc);
        }
        *(u64*)(sKQ + 64 * SP + t2) = acc;
        if (lane == 0) {
            float a = 0.f;
            #pragma unroll 8
            for (int i = 0; i < HH; i++)
                a = fmaf(sK[i * SP + 64], sQ[i * SP + 64], a);
            sKQ[64 * SP + 64] = a;
        }
    }
    __syncwarp();

    // ---- softmax on own rows
    #pragma unroll
    for (int r = 0; r < 4; r++) softmax_row(sKQ + (s0 + r) * SP, lane);
    if (w == 0) softmax_row(sKQ + 64 * SP, lane);
    __syncwarp();

    // ---- O: rows s0..s0+3, i0 = lane*4, packed over i-pairs, chain t ascending
    {
        int i0 = lane << 2;
        u64 o[4][2];
        #pragma unroll
        for (int r = 0; r < 4; r++) { o[r][0] = 0ull; o[r][1] = 0ull; }
        #pragma unroll 1
        for (int tb = 0; tb < SP; tb += 4) {
            float4 q0 = *(const float4*)(sKQ + (s0 + 0) * SP + tb);
            float4 q1 = *(const float4*)(sKQ + (s0 + 1) * SP + tb);
            float4 q2v = *(const float4*)(sKQ + (s0 + 2) * SP + tb);
            float4 q3 = *(const float4*)(sKQ + (s0 + 3) * SP + tb);
            float p0[4] = {q0.x, q0.y, q0.z, q0.w};
            float p1[4] = {q1.x, q1.y, q1.z, q1.w};
            float p2[4] = {q2v.x, q2v.y, q2v.z, q2v.w};
            float p3[4] = {q3.x, q3.y, q3.z, q3.w};
            #pragma unroll
            for (int tt = 0; tt < 4; tt++) {
                ulonglong2 vv = *(const ulonglong2*)(sVt + (tb + tt) * VTS + i0);
                u64 pp;
                pp = pack2(p0[tt], p0[tt]); o[0][0] = fma2(pp, vv.x, o[0][0]); o[0][1] = fma2(pp, vv.y, o[0][1]);
                pp = pack2(p1[tt], p1[tt]); o[1][0] = fma2(pp, vv.x, o[1][0]); o[1][1] = fma2(pp, vv.y, o[1][1]);
                pp = pack2(p2[tt], p2[tt]); o[2][0] = fma2(pp, vv.x, o[2][0]); o[2][1] = fma2(pp, vv.y, o[2][1]);
                pp = pack2(p3[tt], p3[tt]); o[3][0] = fma2(pp, vv.x, o[3][0]); o[3][1] = fma2(pp, vv.y, o[3][1]);
            }
        }
        #pragma unroll
        for (int r = 0; r < 4; r++) {
            ulonglong2 ov; ov.x = o[r][0]; ov.y = o[r][1];
            *(ulonglong2*)(sO + (s0 + r) * HH + i0) = ov;
        }
        // row 64 (warp 0)
        if (w == 0) {
            u64 oa = 0ull, ob = 0ull;
            #pragma unroll 1
            for (int tb = 0; tb < SP; tb += 4) {
                float4 q = *(const float4*)(sKQ + 64 * SP + tb);
                float pr[4] = {q.x, q.y, q.z, q.w};
                #pragma unroll
                for (int tt = 0; tt < 4; tt++) {
                    ulonglong2 vv = *(const ulonglong2*)(sVt + (tb + tt) * VTS + i0);
                    u64 pp = pack2(pr[tt], pr[tt]);
                    oa = fma2(pp, vv.x, oa);
                    ob = fma2(pp, vv.y, ob);
                }
            }
            ulonglong2 o64; o64.x = oa; o64.y = ob;
            *(ulonglong2*)(sO + 64 * HH + i0) = o64;
        }
    }
}

// sZ[s*HH + j] (FIRST: =, else continue chain) sum_i sO[s*HH+i] * L[i*HH+j]
// L staged block-cooperatively into sSB (2 x 2048 floats) via cp.async, 8 chunks
// of 16 i-rows, double-buffered with __syncthreads. Chains unchanged (i ascending).
template <int FIRST>
__device__ __forceinline__ void gemm_Z(const float* __restrict__ sO,
                                       const float* __restrict__ L,
                                       float* __restrict__ sZ,
                                       float* __restrict__ sSB) {
    int tid = threadIdx.x;
    int s0 = (tid >> 5) << 2;        // 0..60
    int j0 = (tid & 31) << 2;        // 0..124
    u32 sbB = (u32)__cvta_generic_to_shared(sSB);
    int crow = tid >> 5;             // 0..15: staging row
    int ccol = (tid & 31) << 2;      // 0..124: staging float4 col

    u64 acc[4][2];
    #pragma unroll
    for (int r = 0; r < 4; r++) {
        if (FIRST) { acc[r][0] = 0ull; acc[r][1] = 0ull; }
        else {
            ulonglong2 z = *(const ulonglong2*)(sZ + (s0 + r) * HH + j0);
            acc[r][0] = z.x; acc[r][1] = z.y;
        }
    }
    // issue chunk 0
    cp16(sbB + ((crow * HH + ccol) << 2), L + crow * HH + ccol);
    CP_COMMIT();
    #pragma unroll 1
    for (int c = 0; c < 8; c++) {
        if (c < 7) {
            cp16(sbB + ((((c + 1) & 1) * 2048 + crow * HH + ccol) << 2),
                 L + ((c + 1) * 16 + crow) * HH + ccol);
            CP_COMMIT();
            CP_WAIT1();
        } else {
            CP_WAIT0();
        }
        __syncthreads();                 // chunk c visible to all
        const float* S = sSB + (c & 1) * 2048;
        #pragma unroll
        for (int ri = 0; ri < 16; ri += 4) {
            int i = c * 16 + ri;
            ulonglong2 l0 = *(const ulonglong2*)(S + (ri + 0) * HH + j0);
            ulonglong2 l1 = *(const ulonglong2*)(S + (ri + 1) * HH + j0);
            ulonglong2 l2 = *(const ulonglong2*)(S + (ri + 2) * HH + j0);
            ulonglong2 l3 = *(const ulonglong2*)(S + (ri + 3) * HH + j0);
            #pragma unroll
            for (int r = 0; r < 4; r++) {
                float4 o = *(const float4*)(sO + (s0 + r) * HH + i);
                ACC_MAT(o, l0, l1, l2, l3, acc[r]);
            }
        }
        __syncthreads();                 // all done reading buf before overwrite
    }
    #pragma unroll
    for (int r = 0; r < 4; r++) {
        ulonglong2 o; o.x = acc[r][0]; o.y = acc[r][1];
        *(ulonglong2*)(sZ + (s0 + r) * HH + j0) = o;
    }
    // tail: s = 64 (same tid -> same element across FIRST/continue)
    if (tid < HH) {
        int j = tid;
        float acc64 = FIRST ? 0.f : sZ[64 * HH + j];
        #pragma unroll 8
        for (int i = 0; i < HH; i++)
            acc64 = fmaf(sO[64 * HH + i], L[i * HH + j], acc64);
        sZ[64 * HH + j] = acc64;
    }
}

// smem layout (floats):
//  P0 @     0 : 8704  Y -> O1 (stride 128)
//  P1 @  8704 : 8704  K0 -> K1 -> Z (stride 128)
//  P2 @ 17408 : 8704  Q0 -> Q1 -> Z-staging (4096) -> Y2
//  P3 @ 26112 : 8976  V0t -> V1t -> q2a
//  P4 @ 35088 : 8704  O0 -> q2b
//  KQ @ 43792 : 4624
//  EX @ 48416 : 1120
//  ST @ 49536 : 6144  per-warp cp.async weight staging (16 x 384)
#define SMEM_FLOATS 55680

__global__ void __launch_bounds__(NT, 1) board_kernel(
    const float* __restrict__ inp, const float* __restrict__ emb,
    const float* __restrict__ wk11, const float* __restrict__ wq11, const float* __restrict__ wv11,
    const float* __restrict__ wk12, const float* __restrict__ wq12, const float* __restrict__ wv12,
    const float* __restrict__ L1,
    const float* __restrict__ wk21, const float* __restrict__ wq21, const float* __restrict__ wv21,
    const float* __restrict__ wk22, const float* __restrict__ wq22, const float* __restrict__ wv22,
    const float* __restrict__ L2, const float* __restrict__ L3, const float* __restrict__ L4,
    float* __restrict__ out) {
    extern __shared__ float sm[];
    float* P0  = sm;
    float* P1  = sm + 8704;
    float* P2  = sm + 17408;
    float* P3  = sm + 26112;
    float* P4  = sm + 35088;
    float* sKQ = sm + 43792;
    float* sEX = sm + 48416;
    float* sST = sm + 49536;

    float* sc   = sEX;          // 2 x 128
    float* sw   = sEX + 256;    // 2 x 72 (stride 72)
    float* syw  = sEX + 416;    // 2 x 128
    float* satt = sEX + 672;    // 256
    float* sh2  = sEX + 928;    // 128
    float* sh3  = sEX + 1056;   // 64

    const int b = blockIdx.x;
    const int tid = threadIdx.x;
    const float* x = inp + (size_t)b * 64;

    // Y[j][s] = emb[j][s] * x[s], x[64]=1; padding cols zero.
    for (int idx = tid; idx < HH * SP; idx += NT) {
        int j = idx / SP, s = idx - j * SP;
        float v = 0.f;
        if (s < 64)       v = emb[j * 65 + s] * x[s];
        else if (s == 64) v = emb[j * 65 + 64];
        P0[idx] = v;
    }
    __syncthreads();

    // ---- layer 1, head 0 ----
    gemm_KQV(wk11, wq11, wv11, P0, P1, P2, P3, sST);   // K0, Q0, V0t
    __syncthreads();
    attn_fused(P1, P2, P3, sKQ, P4);                   // O0 -> P4
    __syncthreads();

    // ---- layer 1, head 1 ----
    gemm_KQV(wk12, wq12, wv12, P0, P1, P2, P3, sST);   // K1, Q1, V1t
    __syncthreads();
    attn_fused(P1, P2, P3, sKQ, P0);                   // O1 -> P0 (Y dead)
    __syncthreads();

    // Z = O0 @ L1[:128] then += O1 @ L1[128:] (single 256-deep in-order chain)
    // L staged through P2 (Q1 dead; Y2 written later).
    gemm_Z<1>(P4, L1,           P1, P2);
    gemm_Z<0>(P0, L1 + HH * HH, P1, P2);
    __syncthreads();

    // tanh + transpose: Y2[j][s] = tanh(Z[s][j]) -> P2
    for (int idx = tid; idx < HH * SP; idx += NT) {
        int j = idx / SP, s = idx - j * SP;
        P2[idx] = (s < SS) ? tanhf(P1[s * HH + j]) : 0.f;
    }
    __syncthreads();

    // ---- layer 2: both heads merged ----
    if (tid < 2 * HH) {                           // c[h][i] = Wk2h[i,:] . y64 (in-order)
        int h = tid >> 7, i = tid & 127;
        const float* Wk = h ? wk22 : wk21;
        float acc = 0.f;
        #pragma unroll 8
        for (int j = 0; j < HH; j++)
            acc = fmaf(Wk[i * HH + j], P2[j * SP + 64], acc);
        sc[(h << 7) + i] = acc;
    }
    gemm_KQ2(wq21, wq22, P2, P3, P4, sST);        // q2a -> P3, q2b -> P4
    __syncthreads();

    if (tid < 2 * SS) {                           // logits[h][t] = c[h] . q2h[:,t]
        int h = tid >= SS, t = tid - (h ? SS : 0);
        const float* q2 = h ? P4 : P3;
        const float* ch = sc + (h << 7);
        float acc = 0.f;
        #pragma unroll 8
        for (int i = 0; i < HH; i++)
            acc = fmaf(ch[i], q2[i * SP + t], acc);
        sw[h * 72 + t] = acc;
    }
    __syncthreads();
    if (tid < 64) {                               // softmax rows (warps 0,1)
        int h = tid >> 5, lane = tid & 31;
        softmax_row(sw + h * 72, lane);
    }
    __syncthreads();
    if (tid < 2 * HH) {                           // yw[h][j] = sum_t w[h][t] * Y2[j][t]
        int h = tid >> 7, j = tid & 127;
        const float* wrow = sw + h * 72;
        float acc = 0.f;
        #pragma unroll
        for (int t = 0; t < SP; t += 4) {
            float4 y4 = *(const float4*)(P2 + j * SP + t);
            float4 w4 = *(const float4*)(wrow + t);
            acc = dot4(y4, w4, acc);
        }
        syw[(h << 7) + j] = acc;
    }
    __syncthreads();
    if (tid < 2 * HH) {                           // att[h][i] = Wv2h[i,:] . yw[h]
        int h = tid >> 7, i = tid & 127;
        const float* Wv = h ? wv22 : wv21;
        const float* yh = syw + (h << 7);
        float acc = 0.f;
        #pragma unroll 8
        for (int j = 0; j < HH; j += 4) {
            float4 w4 = *(const float4*)(Wv + i * HH + j);
            float4 y4 = *(const float4*)(yh + j);
            acc = dot4(w4, y4, acc);
        }
        satt[(h << 7) + i] = acc;
    }
    __syncthreads();

    // head: h2 = tanh(cat(att) @ L2), h3 = tanh(h2 @ L3), score = h3 @ L4
    if (tid < HH) {
        float acc = 0.f;
        #pragma unroll 8
        for (int i = 0; i < 2 * HH; i++)
            acc = fmaf(satt[i], L2[i * HH + tid], acc);
        sh2[tid] = tanhf(acc);
    }
    __syncthreads();
    if (tid < 64) {
        float acc = 0.f;
        #pragma unroll 8
        for (int j = 0; j < HH; j++)
            acc = fmaf(sh2[j], L3[j * 64 + tid], acc);
        sh3[tid] = tanhf(acc);
    }
    __syncthreads();
    if (tid == 0) {
        float acc = 0.f;
        #pragma unroll
        for (int m = 0; m < 64; m++) acc = fmaf(sh3[m], L4[m], acc);
        out[b] = acc;
    }
}

extern "C" void kernel_launch(void* const* d_in, const int* in_sizes, int n_in,
                              void* d_out, int out_size) {
    const float* inputs = (const float*)d_in[0];
    const float* emb    = (const float*)d_in[1];
    const float* wk11   = (const float*)d_in[2];
    const float* wq11   = (const float*)d_in[3];
    const float* wv11   = (const float*)d_in[4];
    const float* wk12   = (const float*)d_in[5];
    const float* wq12   = (const float*)d_in[6];
    const float* wv12   = (const float*)d_in[7];
    const float* L1     = (const float*)d_in[8];
    const float* wk21   = (const float*)d_in[9];
    const float* wq21   = (const float*)d_in[10];
    const float* wv21   = (const float*)d_in[11];
    const float* wk22   = (const float*)d_in[12];
    const float* wq22   = (const float*)d_in[13];
    const float* wv22   = (const float*)d_in[14];
    const float* L2     = (const float*)d_in[15];
    const float* L3     = (const float*)d_in[16];
    const float* L4     = (const float*)d_in[17];
    (void)n_in; (void)in_sizes;

    int B = out_size;  // one score per board (8192)

    size_t smem = SMEM_FLOATS * sizeof(float);
    cudaFuncSetAttribute(board_kernel, cudaFuncAttributeMaxDynamicSharedMemorySize, (int)smem);

    board_kernel<<<B, NT, smem>>>(inputs, emb,
                                  wk11, wq11, wv11, wk12, wq12, wv12, L1,
                                  wk21, wq21, wv21, wk22, wq22, wv22, L2, L3, L4,
                                  (float*)d_out);
}

// round 16
// speedup vs baseline: 1.2543x; 1.0022x over previous
#include <cuda_runtime.h>
#include <math.h>

#define HH 128
#define SS 65
#define SP 68          // padded S stride (cols 65..67 zero where read)
#define VTS 132        // transposed-V stride
#define NT 512

typedef unsigned long long u64;
typedef unsigned int u32;

__device__ __forceinline__ u64 pack2(float lo, float hi) {
    u64 r; asm("mov.b64 %0, {%1, %2};" : "=l"(r) : "f"(lo), "f"(hi)); return r;
}
__device__ __forceinline__ float2 unpack2(u64 p) {
    float2 v; asm("mov.b64 {%0, %1}, %2;" : "=f"(v.x), "=f"(v.y) : "l"(p)); return v;
}
__device__ __forceinline__ u64 fma2(u64 a, u64 b, u64 c) {
    u64 d; asm("fma.rn.f32x2 %0, %1, %2, %3;" : "=l"(d) : "l"(a), "l"(b), "l"(c)); return d;
}
__device__ __forceinline__ float dot4(const float4& a, const float4& b, float acc) {
    acc = fmaf(a.x, b.x, acc);
    acc = fmaf(a.y, b.y, acc);
    acc = fmaf(a.z, b.z, acc);
    acc = fmaf(a.w, b.w, acc);
    return acc;
}

__device__ __forceinline__ void cp16(u32 saddr, const float* g) {
    asm volatile("cp.async.cg.shared.global [%0], [%1], 16;" :: "r"(saddr), "l"(g));
}
#define CP_COMMIT() asm volatile("cp.async.commit_group;" ::: "memory")
#define CP_WAIT1()  asm volatile("cp.async.wait_group 1;" ::: "memory")
#define CP_WAIT0()  asm volatile("cp.async.wait_group 0;" ::: "memory")

#define ACC_MAT(AR, Bx, By, Bz, Bw, ACC)                                              \
    do {                                                                              \
        u64 p_;                                                                       \
        p_ = pack2(AR.x, AR.x); ACC[0] = fma2(p_, Bx.x, ACC[0]); ACC[1] = fma2(p_, Bx.y, ACC[1]); \
        p_ = pack2(AR.y, AR.y); ACC[0] = fma2(p_, By.x, ACC[0]); ACC[1] = fma2(p_, By.y, ACC[1]); \
        p_ = pack2(AR.z, AR.z); ACC[0] = fma2(p_, Bz.x, ACC[0]); ACC[1] = fma2(p_, Bz.y, ACC[1]); \
        p_ = pack2(AR.w, AR.w); ACC[0] = fma2(p_, Bw.x, ACC[0]); ACC[1] = fma2(p_, Bw.y, ACC[1]); \
    } while (0)

// ---- per-warp cp.async staging loaders (no barriers: each warp reads only its slice) ----
// KQV chunk: [3 mats][8 rows][8 k] floats = 192 floats = 48 float4 per stage.
__device__ __forceinline__ void kqv_issue(const float* __restrict__ Wk,
                                          const float* __restrict__ Wq,
                                          const float* __restrict__ Wv,
                                          int jbase, int k0, u32 dstB, int lane) {
    {
        int m = lane >> 4, sub = lane & 15, row = sub >> 1, half = sub & 1;
        const float* W = (m == 0) ? Wk : Wq;
        cp16(dstB + ((m * 64 + row * 8 + half * 4) << 2),
             W + (jbase + row) * HH + k0 + half * 4);
    }
    if (lane < 16) {
        int sub = lane;
        int row = sub >> 1, half = sub & 1;
        cp16(dstB + ((2 * 64 + row * 8 + half * 4) << 2),
             Wv + (jbase + row) * HH + k0 + half * 4);
    }
}
// KQ2 chunk: [2 mats][8 rows][8 k] = 128 floats = 32 float4 per stage.
__device__ __forceinline__ void kq2_issue(const float* __restrict__ Wa,
                                          const float* __restrict__ Wb,
                                          int jbase, int k0, u32 dstB, int lane) {
    int m = lane >> 4, sub = lane & 15, row = sub >> 1, half = sub & 1;
    const float* W = (m == 0) ? Wa : Wb;
    cp16(dstB + ((m * 64 + row * 8 + half * 4) << 2),
         W + (jbase + row) * HH + k0 + half * 4);
}

// Fused K/Q/V projection, one Y sweep, weights staged smem<-L2 via per-warp cp.async.
// Tiles: j0=(tid>>4)<<2, t0=(tid&15)<<2. Chains: k ascending (R13, bit-identical).
__device__ __forceinline__ void gemm_KQV(
    const float* __restrict__ Wk, const float* __restrict__ Wq, const float* __restrict__ Wv,
    const float* __restrict__ sY,
    float* __restrict__ sK, float* __restrict__ sQ, float* __restrict__ sVt,
    float* __restrict__ sStage) {
    {
        int tid = threadIdx.x, w = tid >> 5, lane = tid & 31;
        int j0 = (tid >> 4) << 2;        // 0..124
        int t0 = (tid & 15) << 2;        // 0..60
        int jbase = w << 3;              // warp rows 8w..8w+7
        int lr0 = ((tid >> 4) & 1) << 2; // local row 0 or 4 within warp slice
        float* SW = sStage + w * 384;    // 2 stages x 192 floats
        u32 swB = (u32)__cvta_generic_to_shared(SW);

        u64 aK[4][2], aQ[4][2], aV[4][2];
        #pragma unroll
        for (int r = 0; r < 4; r++) {
            aK[r][0] = aK[r][1] = 0ull;
            aQ[r][0] = aQ[r][1] = 0ull;
            aV[r][0] = aV[r][1] = 0ull;
        }
        kqv_issue(Wk, Wq, Wv, jbase, 0, swB, lane);
        CP_COMMIT();
        #pragma unroll 1
        for (int c = 0; c < 16; c++) {
            if (c < 15) {
                kqv_issue(Wk, Wq, Wv, jbase, (c + 1) * 8, swB + ((c + 1) & 1) * 768, lane);
                CP_COMMIT();
                CP_WAIT1();
            } else {
                CP_WAIT0();
            }
            __syncwarp();
            const float* S = SW + (c & 1) * 192;
            #pragma unroll
            for (int kk = 0; kk < 8; kk += 4) {
                int k = c * 8 + kk;
                ulonglong2 b0 = *(const ulonglong2*)(sY + (k + 0) * SP + t0);
                ulonglong2 b1 = *(const ulonglong2*)(sY + (k + 1) * SP + t0);
                ulonglong2 b2 = *(const ulonglong2*)(sY + (k + 2) * SP + t0);
                ulonglong2 b3 = *(const ulonglong2*)(sY + (k + 3) * SP + t0);
                #pragma unroll
                for (int r = 0; r < 4; r++) {
                    float4 ak = *(const float4*)(S +   0 + (lr0 + r) * 8 + kk);
                    ACC_MAT(ak, b0, b1, b2, b3, aK[r]);
                    float4 aq = *(const float4*)(S +  64 + (lr0 + r) * 8 + kk);
                    ACC_MAT(aq, b0, b1, b2, b3, aQ[r]);
                    float4 av = *(const float4*)(S + 128 + (lr0 + r) * 8 + kk);
                    ACC_MAT(av, b0, b1, b2, b3, aV[r]);
                }
            }
        }
        #pragma unroll
        for (int r = 0; r < 4; r++) {
            ulonglong2 o;
            o.x = aK[r][0]; o.y = aK[r][1]; *(ulonglong2*)(sK + (j0 + r) * SP + t0) = o;
            o.x = aQ[r][0]; o.y = aQ[r][1]; *(ulonglong2*)(sQ + (j0 + r) * SP + t0) = o;
        }
        // V transposed store
        float av4[4][4];
        #pragma unroll
        for (int r = 0; r < 4; r++) {
            float2 lo = unpack2(aV[r][0]), hi = unpack2(aV[r][1]);
            av4[r][0] = lo.x; av4[r][1] = lo.y; av4[r][2] = hi.x; av4[r][3] = hi.y;
        }
        #pragma unroll
        for (int tt = 0; tt < 4; tt++) {
            float4 cc; cc.x = av4[0][tt]; cc.y = av4[1][tt]; cc.z = av4[2][tt]; cc.w = av4[3][tt];
            *(float4*)(sVt + (t0 + tt) * VTS + j0) = cc;
        }
    }
    // tail: t = 64; Vt pad rows zeroed (weights via LDG, small)
    if (threadIdx.x < HH) {
        int j = threadIdx.x;
        float cK = 0.f, cQ = 0.f, cV = 0.f;
        #pragma unroll 4
        for (int k = 0; k < HH; k += 4) {
            float y0 = sY[(k + 0) * SP + 64];
            float y1 = sY[(k + 1) * SP + 64];
            float y2 = sY[(k + 2) * SP + 64];
            float y3 = sY[(k + 3) * SP + 64];
            float4 wk4 = *(const float4*)(Wk + j * HH + k);
            cK = fmaf(wk4.x, y0, cK); cK = fmaf(wk4.y, y1, cK);
            cK = fmaf(wk4.z, y2, cK); cK = fmaf(wk4.w, y3, cK);
            float4 wq4 = *(const float4*)(Wq + j * HH + k);
            cQ = fmaf(wq4.x, y0, cQ); cQ = fmaf(wq4.y, y1, cQ);
            cQ = fmaf(wq4.z, y2, cQ); cQ = fmaf(wq4.w, y3, cQ);
            float4 wv4 = *(const float4*)(Wv + j * HH + k);
            cV = fmaf(wv4.x, y0, cV); cV = fmaf(wv4.y, y1, cV);
            cV = fmaf(wv4.z, y2, cV); cV = fmaf(wv4.w, y3, cV);
        }
        sK[j * SP + 64] = cK;
        sQ[j * SP + 64] = cQ;
        sVt[64 * VTS + j] = cV;
        sVt[65 * VTS + j] = 0.f;
        sVt[66 * VTS + j] = 0.f;
        sVt[67 * VTS + j] = 0.f;
    }
}

// Fused 2-matrix projection (layer-2 q2 both heads), staged weights.
__device__ __forceinline__ void gemm_KQ2(
    const float* __restrict__ Wa, const float* __restrict__ Wb,
    const float* __restrict__ sY,
    float* __restrict__ sA, float* __restrict__ sB2,
    float* __restrict__ sStage) {
    {
        int tid = threadIdx.x, w = tid >> 5, lane = tid & 31;
        int j0 = (tid >> 4) << 2;
        int t0 = (tid & 15) << 2;
        int jbase = w << 3;
        int lr0 = ((tid >> 4) & 1) << 2;
        float* SW = sStage + w * 256;    // 2 stages x 128 floats
        u32 swB = (u32)__cvta_generic_to_shared(SW);

        u64 aA[4][2], aB[4][2];
        #pragma unroll
        for (int r = 0; r < 4; r++) {
            aA[r][0] = aA[r][1] = 0ull;
            aB[r][0] = aB[r][1] = 0ull;
        }
        kq2_issue(Wa, Wb, jbase, 0, swB, lane);
        CP_COMMIT();
        #pragma unroll 1
        for (int c = 0; c < 16; c++) {
            if (c < 15) {
                kq2_issue(Wa, Wb, jbase, (c + 1) * 8, swB + ((c + 1) & 1) * 512, lane);
                CP_COMMIT();
                CP_WAIT1();
            } else {
                CP_WAIT0();
            }
            __syncwarp();
            const float* S = SW + (c & 1) * 128;
            #pragma unroll
            for (int kk = 0; kk < 8; kk += 4) {
                int k = c * 8 + kk;
                ulonglong2 b0 = *(const ulonglong2*)(sY + (k + 0) * SP + t0);
                ulonglong2 b1 = *(const ulonglong2*)(sY + (k + 1) * SP + t0);
                ulonglong2 b2 = *(const ulonglong2*)(sY + (k + 2) * SP + t0);
                ulonglong2 b3 = *(const ulonglong2*)(sY + (k + 3) * SP + t0);
                #pragma unroll
                for (int r = 0; r < 4; r++) {
                    float4 wa = *(const float4*)(S +  0 + (lr0 + r) * 8 + kk);
                    ACC_MAT(wa, b0, b1, b2, b3, aA[r]);
                    float4 wb = *(const float4*)(S + 64 + (lr0 + r) * 8 + kk);
                    ACC_MAT(wb, b0, b1, b2, b3, aB[r]);
                }
            }
        }
        #pragma unroll
        for (int r = 0; r < 4; r++) {
            ulonglong2 o;
            o.x = aA[r][0]; o.y = aA[r][1]; *(ulonglong2*)(sA  + (j0 + r) * SP + t0) = o;
            o.x = aB[r][0]; o.y = aB[r][1]; *(ulonglong2*)(sB2 + (j0 + r) * SP + t0) = o;
        }
    }
    if (threadIdx.x < HH) {
        int j = threadIdx.x;
        float cA = 0.f, cB = 0.f;
        #pragma unroll 4
        for (int k = 0; k < HH; k += 4) {
            float y0 = sY[(k + 0) * SP + 64];
            float y1 = sY[(k + 1) * SP + 64];
            float y2 = sY[(k + 2) * SP + 64];
            float y3 = sY[(k + 3) * SP + 64];
            float4 wa4 = *(const float4*)(Wa + j * HH + k);
            cA = fmaf(wa4.x, y0, cA); cA = fmaf(wa4.y, y1, cA);
            cA = fmaf(wa4.z, y2, cA); cA = fmaf(wa4.w, y3, cA);
            float4 wb4 = *(const float4*)(Wb + j * HH + k);
            cB = fmaf(wb4.x, y0, cB); cB = fmaf(wb4.y, y1, cB);
            cB = fmaf(wb4.z, y2, cB); cB = fmaf(wb4.w, y3, cB);
        }
        sA[j * SP + 64]  = cA;
        sB2[j * SP + 64] = cB;
    }
}

// Row-wise softmax on one row (65 real cols), warp-collective. Zeroes pads.
__device__ __forceinline__ void softmax_row(float* __restrict__ row, int lane) {
    float v0 = row[lane], v1 = row[lane + 32], v2 = row[64];
    float m = fmaxf(fmaxf(v0, v1), v2);
    #pragma unroll
    for (int o = 16; o; o >>= 1) m = fmaxf(m, __shfl_xor_sync(0xffffffffu, m, o));
    float e0 = expf(v0 - m), e1 = expf(v1 - m), e2 = expf(v2 - m);
    float sum = e0 + e1;
    #pragma unroll
    for (int o = 16; o; o >>= 1) sum += __shfl_xor_sync(0xffffffffu, sum, o);
    float denom = sum + e2;
    row[lane] = e0 / denom;
    row[lane + 32] = e1 / denom;
    if (lane == 0) { row[64] = e2 / denom; row[65] = 0.f; row[66] = 0.f; row[67] = 0.f; }
}

// Fused kq -> softmax -> O, barrier-free (warp row-ownership; 16 warps).
// warp w owns rows 4w..4w+3; warp 0 additionally owns row 64 end-to-end.
__device__ __forceinline__ void attn_fused(const float* __restrict__ sK,
                                           const float* __restrict__ sQ,
                                           const float* __restrict__ sVt,
                                           float* __restrict__ sKQ,
                                           float* __restrict__ sO) {
    int tid = threadIdx.x, w = tid >> 5, lane = tid & 31;
    int s0 = w << 2, t2 = lane << 1;

    // ---- kq main: rows s0..s0+3, cols t2, t2+1 (chain i ascending)
    {
        u64 a0 = 0ull, a1 = 0ull, a2 = 0ull, a3 = 0ull;
        #pragma unroll 4
        for (int i = 0; i < HH; i++) {
            float4 kv = *(const float4*)(sK + i * SP + s0);
            u64 q = *(const u64*)(sQ + i * SP + t2);
            a0 = fma2(pack2(kv.x, kv.x), q, a0);
            a1 = fma2(pack2(kv.y, kv.y), q, a1);
            a2 = fma2(pack2(kv.z, kv.z), q, a2);
            a3 = fma2(pack2(kv.w, kv.w), q, a3);
        }
        *(u64*)(sKQ + (s0 + 0) * SP + t2) = a0;
        *(u64*)(sKQ + (s0 + 1) * SP + t2) = a1;
        *(u64*)(sKQ + (s0 + 2) * SP + t2) = a2;
        *(u64*)(sKQ + (s0 + 3) * SP + t2) = a3;
    }
    // col 64 for own rows (lanes 0..3, scalar in-order)
    if (lane < 4) {
        int s = s0 + lane;
        float acc = 0.f;
        #pragma unroll 8
        for (int i = 0; i < HH; i++)
            acc = fmaf(sK[i * SP + s], sQ[i * SP + 64], acc);
        sKQ[s * SP + 64] = acc;
    }
    // row 64 (warp 0): packed pairs per lane + corner by lane 0
    if (w == 0) {
        u64 acc = 0ull;
        #pragma unroll 8
        for (int i = 0; i < HH; i++) {
            float kk = sK[i * SP + 64];
            acc = fma2(pack2(kk, kk), *(const u64*)(sQ + i * SP + t2), acc);
        }
        *(u64*)(sKQ + 64 * SP + t2) = acc;
        if (lane == 0) {
            float a = 0.f;
            #pragma unroll 8
            for (int i = 0; i < HH; i++)
                a = fmaf(sK[i * SP + 64], sQ[i * SP + 64], a);
            sKQ[64 * SP + 64] = a;
        }
    }
    __syncwarp();

    // ---- softmax on own rows
    #pragma unroll
    for (int r = 0; r < 4; r++) softmax_row(sKQ + (s0 + r) * SP, lane);
    if (w == 0) softmax_row(sKQ + 64 * SP, lane);
    __syncwarp();

    // ---- O: rows s0..s0+3, i0 = lane*4, packed over i-pairs, chain t ascending
    {
        int i0 = lane << 2;
        u64 o[4][2];
        #pragma unroll
        for (int r = 0; r < 4; r++) { o[r][0] = 0ull; o[r][1] = 0ull; }
        #pragma unroll 1
        for (int tb = 0; tb < SP; tb += 4) {
            float4 q0 = *(const float4*)(sKQ + (s0 + 0) * SP + tb);
            float4 q1 = *(const float4*)(sKQ + (s0 + 1) * SP + tb);
            float4 q2v = *(const float4*)(sKQ + (s0 + 2) * SP + tb);
            float4 q3 = *(const float4*)(sKQ + (s0 + 3) * SP + tb);
            float p0[4] = {q0.x, q0.y, q0.z, q0.w};
            float p1[4] = {q1.x, q1.y, q1.z, q1.w};
            float p2[4] = {q2v.x, q2v.y, q2v.z, q2v.w};
            float p3[4] = {q3.x, q3.y, q3.z, q3.w};
            #pragma unroll
            for (int tt = 0; tt < 4; tt++) {
                ulonglong2 vv = *(const ulonglong2*)(sVt + (tb + tt) * VTS + i0);
                u64 pp;
                pp = pack2(p0[tt], p0[tt]); o[0][0] = fma2(pp, vv.x, o[0][0]); o[0][1] = fma2(pp, vv.y, o[0][1]);
                pp = pack2(p1[tt], p1[tt]); o[1][0] = fma2(pp, vv.x, o[1][0]); o[1][1] = fma2(pp, vv.y, o[1][1]);
                pp = pack2(p2[tt], p2[tt]); o[2][0] = fma2(pp, vv.x, o[2][0]); o[2][1] = fma2(pp, vv.y, o[2][1]);
                pp = pack2(p3[tt], p3[tt]); o[3][0] = fma2(pp, vv.x, o[3][0]); o[3][1] = fma2(pp, vv.y, o[3][1]);
            }
        }
        #pragma unroll
        for (int r = 0; r < 4; r++) {
            ulonglong2 ov; ov.x = o[r][0]; ov.y = o[r][1];
            *(ulonglong2*)(sO + (s0 + r) * HH + i0) = ov;
        }
        // row 64 (warp 0)
        if (w == 0) {
            u64 oa = 0ull, ob = 0ull;
            #pragma unroll 1
            for (int tb = 0; tb < SP; tb += 4) {
                float4 q = *(const float4*)(sKQ + 64 * SP + tb);
                float pr[4] = {q.x, q.y, q.z, q.w};
                #pragma unroll
                for (int tt = 0; tt < 4; tt++) {
                    ulonglong2 vv = *(const ulonglong2*)(sVt + (tb + tt) * VTS + i0);
                    u64 pp = pack2(pr[tt], pr[tt]);
                    oa = fma2(pp, vv.x, oa);
                    ob = fma2(pp, vv.y, ob);
                }
            }
            ulonglong2 o64; o64.x = oa; o64.y = ob;
            *(ulonglong2*)(sO + 64 * HH + i0) = o64;
        }
    }
}

// Z[s*HH+j] = sum_{i=0..255} Ocat[s][i] * L1[i*HH+j], single pass over both O halves.
// 16 chunks of 16 L-rows staged via cp.async into sSB (2 x 2048). Chunks 0..7 read
// sO0, 8..15 read sO1. Chain = O0 i-ascending then O1 i-ascending — bit-identical
// to the former gemm_Z<1>/gemm_Z<0> pair (whose Z store/reload was exact fp32).
__device__ __forceinline__ void gemm_Z256(const float* __restrict__ sO0,
                                          const float* __restrict__ sO1,
                                          const float* __restrict__ L,
                                          float* __restrict__ sZ,
                                          float* __restrict__ sSB) {
    int tid = threadIdx.x;
    int s0 = (tid >> 5) << 2;        // 0..60
    int j0 = (tid & 31) << 2;        // 0..124
    u32 sbB = (u32)__cvta_generic_to_shared(sSB);
    int crow = tid >> 5;             // 0..15: staging row
    int ccol = (tid & 31) << 2;      // staging float4 col

    u64 acc[4][2];
    #pragma unroll
    for (int r = 0; r < 4; r++) { acc[r][0] = 0ull; acc[r][1] = 0ull; }

    cp16(sbB + ((crow * HH + ccol) << 2), L + crow * HH + ccol);
    CP_COMMIT();
    #pragma unroll 1
    for (int c = 0; c < 16; c++) {
        if (c < 15) {
            cp16(sbB + ((((c + 1) & 1) * 2048 + crow * HH + ccol) << 2),
                 L + ((c + 1) * 16 + crow) * HH + ccol);
            CP_COMMIT();
            CP_WAIT1();
        } else {
            CP_WAIT0();
        }
        __syncthreads();                 // chunk c visible to all
        const float* S = sSB + (c & 1) * 2048;
        const float* sO = (c < 8) ? sO0 : sO1;
        int ibase = (c & 7) * 16;
        #pragma unroll
        for (int ri = 0; ri < 16; ri += 4) {
            int i = ibase + ri;
            ulonglong2 l0 = *(const ulonglong2*)(S + (ri + 0) * HH + j0);
            ulonglong2 l1 = *(const ulonglong2*)(S + (ri + 1) * HH + j0);
            ulonglong2 l2 = *(const ulonglong2*)(S + (ri + 2) * HH + j0);
            ulonglong2 l3 = *(const ulonglong2*)(S + (ri + 3) * HH + j0);
            #pragma unroll
            for (int r = 0; r < 4; r++) {
                float4 o = *(const float4*)(sO + (s0 + r) * HH + i);
                ACC_MAT(o, l0, l1, l2, l3, acc[r]);
            }
        }
        __syncthreads();                 // all done reading buf before overwrite
    }
    #pragma unroll
    for (int r = 0; r < 4; r++) {
        ulonglong2 o; o.x = acc[r][0]; o.y = acc[r][1];
        *(ulonglong2*)(sZ + (s0 + r) * HH + j0) = o;
    }
    // tail: s = 64, single 256-deep in-order chain
    if (tid < HH) {
        int j = tid;
        float acc64 = 0.f;
        #pragma unroll 8
        for (int i = 0; i < HH; i++)
            acc64 = fmaf(sO0[64 * HH + i], L[i * HH + j], acc64);
        #pragma unroll 8
        for (int i = 0; i < HH; i++)
            acc64 = fmaf(sO1[64 * HH + i], L[(HH + i) * HH + j], acc64);
        sZ[64 * HH + j] = acc64;
    }
}

// smem layout (floats):
//  P0 @     0 : 8704  Y -> O1 (stride 128)
//  P1 @  8704 : 8704  K0 -> K1 -> Z (stride 128)
//  P2 @ 17408 : 8704  Q0 -> Q1 -> Z-staging(4096) -> Y2
//  P3 @ 26112 : 8976  V0t -> V1t -> q2a
//  P4 @ 35088 : 8704  O0 -> q2b
//  KQ @ 43792 : 4624
//  EX @ 48416 : 1120
//  ST @ 49536 : 6144  per-warp cp.async weight staging (16 x 384)
#define SMEM_FLOATS 55680

__global__ void __launch_bounds__(NT, 1) board_kernel(
    const float* __restrict__ inp, const float* __restrict__ emb,
    const float* __restrict__ wk11, const float* __restrict__ wq11, const float* __restrict__ wv11,
    const float* __restrict__ wk12, const float* __restrict__ wq12, const float* __restrict__ wv12,
    const float* __restrict__ L1,
    const float* __restrict__ wk21, const float* __restrict__ wq21, const float* __restrict__ wv21,
    const float* __restrict__ wk22, const float* __restrict__ wq22, const float* __restrict__ wv22,
    const float* __restrict__ L2, const float* __restrict__ L3, const float* __restrict__ L4,
    float* __restrict__ out) {
    extern __shared__ float sm[];
    float* P0  = sm;
    float* P1  = sm + 8704;
    float* P2  = sm + 17408;
    float* P3  = sm + 26112;
    float* P4  = sm + 35088;
    float* sKQ = sm + 43792;
    float* sEX = sm + 48416;
    float* sST = sm + 49536;

    float* sc   = sEX;          // 2 x 128
    float* sw   = sEX + 256;    // 2 x 72 (stride 72)
    float* syw  = sEX + 416;    // 2 x 128
    float* satt = sEX + 672;    // 256
    float* sh2  = sEX + 928;    // 128
    float* sh3  = sEX + 1056;   // 64

    const int b = blockIdx.x;
    const int tid = threadIdx.x;
    const float* x = inp + (size_t)b * 64;

    // Y[j][s] = emb[j][s] * x[s], x[64]=1; padding cols zero.
    for (int idx = tid; idx < HH * SP; idx += NT) {
        int j = idx / SP, s = idx - j * SP;
        float v = 0.f;
        if (s < 64)       v = emb[j * 65 + s] * x[s];
        else if (s == 64) v = emb[j * 65 + 64];
        P0[idx] = v;
    }
    __syncthreads();

    // ---- layer 1, head 0 ----
    gemm_KQV(wk11, wq11, wv11, P0, P1, P2, P3, sST);   // K0, Q0, V0t
    __syncthreads();
    attn_fused(P1, P2, P3, sKQ, P4);                   // O0 -> P4
    __syncthreads();

    // ---- layer 1, head 1 ----
    gemm_KQV(wk12, wq12, wv12, P0, P1, P2, P3, sST);   // K1, Q1, V1t
    __syncthreads();
    attn_fused(P1, P2, P3, sKQ, P0);                   // O1 -> P0 (Y dead)
    __syncthreads();

    // Z = [O0 | O1] @ L1 in one staged pass (single 256-deep in-order chain)
    gemm_Z256(P4, P0, L1, P1, P2);
    __syncthreads();

    // tanh + transpose: Y2[j][s] = tanh(Z[s][j]) -> P2
    for (int idx = tid; idx < HH * SP; idx += NT) {
        int j = idx / SP, s = idx - j * SP;
        P2[idx] = (s < SS) ? tanhf(P1[s * HH + j]) : 0.f;
    }
    __syncthreads();

    // ---- layer 2: both heads merged ----
    if (tid < 2 * HH) {                           // c[h][i] = Wk2h[i,:] . y64 (in-order)
        int h = tid >> 7, i = tid & 127;
        const float* Wk = h ? wk22 : wk21;
        float acc = 0.f;
        #pragma unroll 8
        for (int j = 0; j < HH; j++)
            acc = fmaf(Wk[i * HH + j], P2[j * SP + 64], acc);
        sc[(h << 7) + i] = acc;
    }
    gemm_KQ2(wq21, wq22, P2, P3, P4, sST);        // q2a -> P3, q2b -> P4
    __syncthreads();

    if (tid < 2 * SS) {                           // logits[h][t] = c[h] . q2h[:,t]
        int h = tid >= SS, t = tid - (h ? SS : 0);
        const float* q2 = h ? P4 : P3;
        const float* ch = sc + (h << 7);
        float acc = 0.f;
        #pragma unroll 8
        for (int i = 0; i < HH; i++)
            acc = fmaf(ch[i], q2[i * SP + t], acc);
        sw[h * 72 + t] = acc;
    }
    __syncthreads();
    if (tid < 64) {                               // softmax rows (warps 0,1)
        int h = tid >> 5, lane = tid & 31;
        softmax_row(sw + h * 72, lane);
    }
    __syncthreads();
    if (tid < 2 * HH) {                           // yw[h][j] = sum_t w[h][t] * Y2[j][t]
        int h = tid >> 7, j = tid & 127;
        const float* wrow = sw + h * 72;
        float acc = 0.f;
        #pragma unroll
        for (int t = 0; t < SP; t += 4) {
            float4 y4 = *(const float4*)(P2 + j * SP + t);
            float4 w4 = *(const float4*)(wrow + t);
            acc = dot4(y4, w4, acc);
        }
        syw[(h << 7) + j] = acc;
    }
    __syncthreads();
    if (tid < 2 * HH) {                           // att[h][i] = Wv2h[i,:] . yw[h]
        int h = tid >> 7, i = tid & 127;
        const float* Wv = h ? wv22 : wv21;
        const float* yh = syw + (h << 7);
        float acc = 0.f;
        #pragma unroll 8
        for (int j = 0; j < HH; j += 4) {
            float4 w4 = *(const float4*)(Wv + i * HH + j);
            float4 y4 = *(const float4*)(yh + j);
            acc = dot4(w4, y4, acc);
        }
        satt[(h << 7) + i] = acc;
    }
    __syncthreads();

    // head: h2 = tanh(cat(att) @ L2), h3 = tanh(h2 @ L3), score = h3 @ L4
    if (tid < HH) {
        float acc = 0.f;
        #pragma unroll 8
        for (int i = 0; i < 2 * HH; i++)
            acc = fmaf(satt[i], L2[i * HH + tid], acc);
        sh2[tid] = tanhf(acc);
    }
    __syncthreads();
    if (tid < 64) {
        float acc = 0.f;
        #pragma unroll 8
        for (int j = 0; j < HH; j++)
            acc = fmaf(sh2[j], L3[j * 64 + tid], acc);
        sh3[tid] = tanhf(acc);
    }
    __syncthreads();
    if (tid == 0) {
        float acc = 0.f;
        #pragma unroll
        for (int m = 0; m < 64; m++) acc = fmaf(sh3[m], L4[m], acc);
        out[b] = acc;
    }
}

extern "C" void kernel_launch(void* const* d_in, const int* in_sizes, int n_in,
                              void* d_out, int out_size) {
    const float* inputs = (const float*)d_in[0];
    const float* emb    = (const float*)d_in[1];
    const float* wk11   = (const float*)d_in[2];
    const float* wq11   = (const float*)d_in[3];
    const float* wv11   = (const float*)d_in[4];
    const float* wk12   = (const float*)d_in[5];
    const float* wq12   = (const float*)d_in[6];
    const float* wv12   = (const float*)d_in[7];
    const float* L1     = (const float*)d_in[8];
    const float* wk21   = (const float*)d_in[9];
    const float* wq21   = (const float*)d_in[10];
    const float* wv21   = (const float*)d_in[11];
    const float* wk22   = (const float*)d_in[12];
    const float* wq22   = (const float*)d_in[13];
    const float* wv22   = (const float*)d_in[14];
    const float* L2     = (const float*)d_in[15];
    const float* L3     = (const float*)d_in[16];
    const float* L4     = (const float*)d_in[17];
    (void)n_in; (void)in_sizes;

    int B = out_size;  // one score per board (8192)

    size_t smem = SMEM_FLOATS * sizeof(float);
    cudaFuncSetAttribute(board_kernel, cudaFuncAttributeMaxDynamicSharedMemorySize, (int)smem);

    board_kernel<<<B, NT, smem>>>(inputs, emb,
                                  wk11, wq11, wv11, wk12, wq12, wv12, L1,
                                  wk21, wq21, wv21, wk22, wq22, wv22, L2, L3, L4,
                                  (float*)d_out);
}